// round 7
// baseline (speedup 1.0000x reference)
#include <cuda_runtime.h>
#include <cuda_bf16.h>

typedef unsigned long long ull;

// ---------------- problem constants (fixed shapes per reference) -------------
#define NMAX   50000
#define EMAX   1250000
#define GMAX   1024
#define LD     32      // label/embedding dim
#define HD     64      // hidden dim

// ---------------- device scratch (no allocation allowed) --------------------
__device__ float g_h0 [NMAX * LD];   // embedded labels
__device__ float g_ag0[NMAX * LD];   // layer0 aggregation
__device__ float g_h1 [NMAX * HD];   // layer0 output h
__device__ float g_ag1[NMAX * HD];   // layer1 aggregation
__device__ float g_a  [NMAX * HD];   // MLP intermediate
__device__ float g_sum[GMAX * HD];   // per-graph feature sums
__device__ float g_cnt[GMAX];        // per-graph node counts

// ---------------- packed f32x2 helpers (Blackwell FFMA2) --------------------
__device__ __forceinline__ void fma2(ull& acc, ull a, ull b) {
    asm("fma.rn.f32x2 %0, %1, %2, %0;" : "+l"(acc) : "l"(a), "l"(b));
}
__device__ __forceinline__ ull pack_dup(float x) {
    ull r;
    asm("mov.b64 %0, {%1, %1};" : "=l"(r) : "r"(__float_as_uint(x)));
    return r;
}
__device__ __forceinline__ float2 unpack2(ull v) {
    unsigned lo, hi;
    asm("mov.b64 {%0, %1}, %2;" : "=r"(lo), "=r"(hi) : "l"(v));
    return make_float2(__uint_as_float(lo), __uint_as_float(hi));
}

// ---------------- init: embedding lookup + zero all accumulators ------------
__global__ void init_kernel(const int* __restrict__ labels,
                            const float* __restrict__ emb,
                            int n, int g, int max_label,
                            float* __restrict__ h0, float* __restrict__ ag0,
                            float* __restrict__ ag1,
                            float* __restrict__ sums, float* __restrict__ cnts)
{
    int idx = blockIdx.x * blockDim.x + threadIdx.x;
    if (idx < n * LD) {
        int node = idx >> 5;
        int d    = idx & (LD - 1);
        int lab  = labels[node];
        lab = lab < 0 ? 0 : (lab > max_label ? max_label : lab);
        h0[idx]  = emb[lab * LD + d];
        ag0[idx] = 0.f;
    }
    if (idx < n * HD) ag1[idx] = 0.f;
    if (idx < g * HD) sums[idx] = 0.f;
    if (idx < g)      cnts[idx] = 0.f;
}

// ---------------- edge scatter: agg[dst] += h[src] (vector atomics) ---------
template <int DIM>
__global__ void scatter_kernel(const int* __restrict__ src,
                               const int* __restrict__ dst,
                               const float* __restrict__ h,
                               float* __restrict__ agg, int E)
{
    const int J = DIM / 4;
    int idx = blockIdx.x * blockDim.x + threadIdx.x;
    if (idx >= E * J) return;
    int e = idx / J;
    int j = idx - e * J;
    int s = __ldg(&src[e]);
    int d = __ldg(&dst[e]);
    float4 v = *reinterpret_cast<const float4*>(h + (size_t)s * DIM + j * 4);
    atomicAdd(reinterpret_cast<float4*>(agg + (size_t)d * DIM + j * 4), v);
}

// ---------------- FFMA2 register-tiled GEMM half-layer ----------------------
// out[128-node tile, 64 feats] = relu(bias + (x1[+x2]) @ W)  (W: [K][64] row-major)
// 256 threads; thread = 4 nodes x 8 features as 4x4 packed f32x2 accumulators.
// tn = lane -> Xs LDS.128 lane-contiguous (conflict-free); W reads broadcast.
template <int K, bool ADD2, bool POOL>
__global__ void __launch_bounds__(256)
gemm_kernel(const float* __restrict__ x1, const float* __restrict__ x2,
            const float* __restrict__ W, const float* __restrict__ bias,
            float* __restrict__ out,
            const int* __restrict__ gids,
            float* __restrict__ sums, float* __restrict__ cnts, int n)
{
    const int XP = 132;                 // padded row pitch (floats) for Xs
    __shared__ float Xs[32 * XP];       // one 32-k chunk of X, transposed [k][node]
    __shared__ float Ws[K * HD];        // full W
    __shared__ float bs[HD];

    const int tid = threadIdx.x;
    const int node_base = blockIdx.x * 128;

    // stage W + bias once
    {
        const float4* Wg = reinterpret_cast<const float4*>(W);
        float4* Wsm4 = reinterpret_cast<float4*>(Ws);
#pragma unroll
        for (int i = tid; i < K * HD / 4; i += 256) Wsm4[i] = Wg[i];
    }
    if (tid < HD) bs[tid] = bias[tid];

    const int tn = tid & 31;            // node group: 4 nodes (lane-contiguous)
    const int tf = tid >> 5;            // feature group: 8 feats = 4 f32x2

    ull acc[4][4];
    bool acc_init = false;

    for (int kc = 0; kc < K; kc += 32) {
        if (kc > 0) __syncthreads();    // protect Xs reuse
        // stage Xs[kk][node] for kk in [0,32): 128 nodes x 8 float4 chunks
#pragma unroll
        for (int i = tid; i < 128 * 8; i += 256) {
            int nn = i & 127;
            int c  = i >> 7;            // float4 chunk -> k offset c*4
            int node = node_base + nn;
            float4 v = make_float4(0.f, 0.f, 0.f, 0.f);
            if (node < n) {
                v = *reinterpret_cast<const float4*>(x1 + (size_t)node * K + kc + c * 4);
                if (ADD2) {
                    float4 u = *reinterpret_cast<const float4*>(x2 + (size_t)node * K + kc + c * 4);
                    v.x += u.x; v.y += u.y; v.z += u.z; v.w += u.w;
                }
            }
            Xs[(c * 4 + 0) * XP + nn] = v.x;
            Xs[(c * 4 + 1) * XP + nn] = v.y;
            Xs[(c * 4 + 2) * XP + nn] = v.z;
            Xs[(c * 4 + 3) * XP + nn] = v.w;
        }
        __syncthreads();

        if (!acc_init) {
            acc_init = true;
            ulonglong2 b01 = *reinterpret_cast<const ulonglong2*>(bs + tf * 8);
            ulonglong2 b23 = *reinterpret_cast<const ulonglong2*>(bs + tf * 8 + 4);
#pragma unroll
            for (int i = 0; i < 4; i++) {
                acc[i][0] = b01.x; acc[i][1] = b01.y;
                acc[i][2] = b23.x; acc[i][3] = b23.y;
            }
        }

#pragma unroll 8
        for (int kk = 0; kk < 32; kk++) {
            float4 xv = *reinterpret_cast<const float4*>(Xs + kk * XP + tn * 4);
            const float* wrow = Ws + (kc + kk) * HD + tf * 8;
            ulonglong2 w01 = *reinterpret_cast<const ulonglong2*>(wrow);
            ulonglong2 w23 = *reinterpret_cast<const ulonglong2*>(wrow + 4);
            ull xd[4] = {pack_dup(xv.x), pack_dup(xv.y), pack_dup(xv.z), pack_dup(xv.w)};
#pragma unroll
            for (int i = 0; i < 4; i++) {
                fma2(acc[i][0], xd[i], w01.x);
                fma2(acc[i][1], xd[i], w01.y);
                fma2(acc[i][2], xd[i], w23.x);
                fma2(acc[i][3], xd[i], w23.y);
            }
        }
    }

    // epilogue
#pragma unroll
    for (int i = 0; i < 4; i++) {
        int node = node_base + tn * 4 + i;
        if (node >= n) continue;
        float2 p0 = unpack2(acc[i][0]);
        float2 p1 = unpack2(acc[i][1]);
        float2 p2 = unpack2(acc[i][2]);
        float2 p3 = unpack2(acc[i][3]);
        float4 ra = make_float4(fmaxf(p0.x, 0.f), fmaxf(p0.y, 0.f),
                                fmaxf(p1.x, 0.f), fmaxf(p1.y, 0.f));
        float4 rb = make_float4(fmaxf(p2.x, 0.f), fmaxf(p2.y, 0.f),
                                fmaxf(p3.x, 0.f), fmaxf(p3.y, 0.f));
        if (!POOL) {
            float* o = out + (size_t)node * HD + tf * 8;
            *reinterpret_cast<float4*>(o)     = ra;
            *reinterpret_cast<float4*>(o + 4) = rb;
        } else {
            int g = gids[node];
            float* sg = sums + (size_t)g * HD + tf * 8;
            atomicAdd(reinterpret_cast<float4*>(sg),     ra);
            atomicAdd(reinterpret_cast<float4*>(sg + 4), rb);
            if (tf == 0) atomicAdd(&cnts[g], 1.0f);
        }
    }
}

// ---------------- scorer: out[g] = relu(mean_h @ sw1 + sb1) @ sw2 + sb2 -----
__global__ void scorer_kernel(const float* __restrict__ sums,
                              const float* __restrict__ cnts,
                              const float* __restrict__ sw1,
                              const float* __restrict__ sb1,
                              const float* __restrict__ sw2,
                              const float* __restrict__ sb2,
                              float* __restrict__ out)
{
    int g = blockIdx.x;
    int f = threadIdx.x;           // 64 threads
    float cnt = fmaxf(cnts[g], 1.0f);
    float inv = 1.0f / cnt;
    float acc = sb1[f];
    const float* sg = sums + (size_t)g * HD;
    for (int k = 0; k < HD; k++) acc += (sg[k] * inv) * sw1[k * HD + f];
    float hf = fmaxf(acc, 0.f) * sw2[f];

    __shared__ float red[HD];
    red[f] = hf;
    __syncthreads();
    if (f < 32) red[f] += red[f + 32];
    __syncthreads();
    if (f < 32) {
        float v = red[f];
#pragma unroll
        for (int off = 16; off > 0; off >>= 1)
            v += __shfl_down_sync(0xFFFFFFFFu, v, off);
        if (f == 0) out[g] = v + sb2[0];
    }
}

// ---------------- launcher --------------------------------------------------
extern "C" void kernel_launch(void* const* d_in, const int* in_sizes, int n_in,
                              void* d_out, int out_size)
{
    const int*   labels = (const int*)  d_in[0];
    const int*   src    = (const int*)  d_in[1];
    const int*   dst    = (const int*)  d_in[2];
    const int*   gids   = (const int*)  d_in[3];
    const float* emb    = (const float*)d_in[4];
    const float* w1_0   = (const float*)d_in[5];
    const float* b1_0   = (const float*)d_in[6];
    const float* w2_0   = (const float*)d_in[7];
    const float* b2_0   = (const float*)d_in[8];
    const float* w1_1   = (const float*)d_in[9];
    const float* b1_1   = (const float*)d_in[10];
    const float* w2_1   = (const float*)d_in[11];
    const float* b2_1   = (const float*)d_in[12];
    const float* sw1    = (const float*)d_in[13];
    const float* sb1    = (const float*)d_in[14];
    const float* sw2    = (const float*)d_in[15];
    const float* sb2    = (const float*)d_in[16];
    float* out = (float*)d_out;

    int N = in_sizes[0];
    int E = in_sizes[1];
    int G = out_size;
    int max_label = in_sizes[4] / LD - 1;

    if (N > NMAX) N = NMAX;
    if (E > EMAX) E = EMAX;
    if (G > GMAX) G = GMAX;

    float *h0, *ag0, *h1, *ag1, *a, *sums, *cnts;
    cudaGetSymbolAddress((void**)&h0,   g_h0);
    cudaGetSymbolAddress((void**)&ag0,  g_ag0);
    cudaGetSymbolAddress((void**)&h1,   g_h1);
    cudaGetSymbolAddress((void**)&ag1,  g_ag1);
    cudaGetSymbolAddress((void**)&a,    g_a);
    cudaGetSymbolAddress((void**)&sums, g_sum);
    cudaGetSymbolAddress((void**)&cnts, g_cnt);

    const int TB = 256;
    const int NB = (N + 127) / 128;   // GEMM node tiles

    // 1. embedding + zero accumulators
    init_kernel<<<(N * HD + TB - 1) / TB, TB>>>(labels, emb, N, G, max_label,
                                                h0, ag0, ag1, sums, cnts);
    // 2. layer0 scatter: ag0[dst] += h0[src]  (32-dim)
    scatter_kernel<LD><<<(E * (LD / 4) + TB - 1) / TB, TB>>>(src, dst, h0, ag0, E);
    // 3. layer0 MLP
    gemm_kernel<LD, true , false><<<NB, 256>>>(h0, ag0, w1_0, b1_0, a,  nullptr, nullptr, nullptr, N);
    gemm_kernel<HD, false, false><<<NB, 256>>>(a,  nullptr, w2_0, b2_0, h1, nullptr, nullptr, nullptr, N);
    // 4. layer1 scatter: ag1[dst] += h1[src]  (64-dim)
    scatter_kernel<HD><<<(E * (HD / 4) + TB - 1) / TB, TB>>>(src, dst, h1, ag1, E);
    // 5. layer1 MLP + fused mean-pool accumulation
    gemm_kernel<HD, true , false><<<NB, 256>>>(h1, ag1, w1_1, b1_1, a, nullptr, nullptr, nullptr, N);
    gemm_kernel<HD, false, true ><<<NB, 256>>>(a,  nullptr, w2_1, b2_1, nullptr, gids, sums, cnts, N);
    // 6. scorer
    scorer_kernel<<<G, HD>>>(sums, cnts, sw1, sb1, sw2, sb2, out);
}

// round 8
// speedup vs baseline: 1.0723x; 1.0723x over previous
#include <cuda_runtime.h>
#include <cuda_bf16.h>

typedef unsigned long long ull;

// ---------------- problem constants (fixed shapes per reference) -------------
#define NMAX   50000
#define EMAX   1250000
#define GMAX   1024
#define LD     32      // label/embedding dim
#define HD     64      // hidden dim

// ---------------- device scratch (no allocation allowed) --------------------
__device__ float g_h0 [NMAX * LD];   // embedded labels
__device__ float g_ag0[NMAX * LD];   // layer0 aggregation
__device__ float g_h1 [NMAX * HD];   // layer0 output h
__device__ float g_ag1[NMAX * HD];   // layer1 aggregation
__device__ float g_sum[GMAX * HD];   // per-graph feature sums
__device__ float g_cnt[GMAX];        // per-graph node counts

// ---------------- packed f32x2 helpers (Blackwell FFMA2) --------------------
__device__ __forceinline__ void fma2(ull& acc, ull a, ull b) {
    asm("fma.rn.f32x2 %0, %1, %2, %0;" : "+l"(acc) : "l"(a), "l"(b));
}
__device__ __forceinline__ ull pack_dup(float x) {
    ull r;
    asm("mov.b64 %0, {%1, %1};" : "=l"(r) : "r"(__float_as_uint(x)));
    return r;
}
__device__ __forceinline__ float2 unpack2(ull v) {
    unsigned lo, hi;
    asm("mov.b64 {%0, %1}, %2;" : "=r"(lo), "=r"(hi) : "l"(v));
    return make_float2(__uint_as_float(lo), __uint_as_float(hi));
}

// ---------------- init: embedding lookup + zero all accumulators ------------
__global__ void init_kernel(const int* __restrict__ labels,
                            const float* __restrict__ emb,
                            int n, int g, int max_label,
                            float* __restrict__ h0, float* __restrict__ ag0,
                            float* __restrict__ ag1,
                            float* __restrict__ sums, float* __restrict__ cnts)
{
    int idx = blockIdx.x * blockDim.x + threadIdx.x;
    if (idx < n * LD) {
        int node = idx >> 5;
        int d    = idx & (LD - 1);
        int lab  = labels[node];
        lab = lab < 0 ? 0 : (lab > max_label ? max_label : lab);
        h0[idx]  = emb[lab * LD + d];
        ag0[idx] = 0.f;
    }
    if (idx < n * HD) ag1[idx] = 0.f;
    if (idx < g * HD) sums[idx] = 0.f;
    if (idx < g)      cnts[idx] = 0.f;
}

// ---------------- edge scatter: agg[dst] += h[src] (vector atomics) ---------
template <int DIM>
__global__ void scatter_kernel(const int* __restrict__ src,
                               const int* __restrict__ dst,
                               const float* __restrict__ h,
                               float* __restrict__ agg, int E)
{
    const int J = DIM / 4;
    int idx = blockIdx.x * blockDim.x + threadIdx.x;
    if (idx >= E * J) return;
    int e = idx / J;
    int j = idx - e * J;
    int s = __ldg(&src[e]);
    int d = __ldg(&dst[e]);
    float4 v = *reinterpret_cast<const float4*>(h + (size_t)s * DIM + j * 4);
    atomicAdd(reinterpret_cast<float4*>(agg + (size_t)d * DIM + j * 4), v);
}

// ---------------- fused 2-layer MLP (one GIN MLP) ----------------------------
// For a 128-node tile:
//   phase 1: a = relu((x1[+x2]) @ W1 + b1)   -> smem As (transposed [feat][node])
//   phase 2: y = relu(a @ W2 + b2)           -> global out, or pooled (POOL)
// 256 threads; thread = 4 nodes (lane-contiguous) x 8 feats, FFMA2 accumulators.
// W/bias read via uniform-address LDG.128 (warp broadcast, L1-resident).
template <int K1, bool ADD2, bool POOL>
__global__ void __launch_bounds__(256)
mlp2_kernel(const float* __restrict__ x1, const float* __restrict__ x2,
            const float* __restrict__ W1, const float* __restrict__ b1,
            const float* __restrict__ W2, const float* __restrict__ b2,
            float* __restrict__ out,
            const int* __restrict__ gids,
            float* __restrict__ sums, float* __restrict__ cnts, int n)
{
    const int XP = 132;                 // row pitch (floats)
    __shared__ float As[HD * XP];       // intermediate, transposed [k2][node]
    __shared__ float Xs[16 * XP];       // 16-k staging chunk of X, [k][node]

    const int tid = threadIdx.x;
    const int node_base = blockIdx.x * 128;
    const int tn = tid & 31;            // node group: 4 lane-contiguous nodes
    const int tf = tid >> 5;            // feature group: 8 feats = 4 f32x2

    ull acc[4][4];
    {   // init with b1
        ulonglong2 b01 = *reinterpret_cast<const ulonglong2*>(b1 + tf * 8);
        ulonglong2 b23 = *reinterpret_cast<const ulonglong2*>(b1 + tf * 8 + 4);
#pragma unroll
        for (int i = 0; i < 4; i++) {
            acc[i][0] = b01.x; acc[i][1] = b01.y;
            acc[i][2] = b23.x; acc[i][3] = b23.y;
        }
    }

    // ---------------- phase 1: x @ W1 ----------------
    for (int kc = 0; kc < K1; kc += 16) {
        if (kc > 0) __syncthreads();    // protect Xs reuse
        // stage Xs[kk][node] for kk in [0,16): 128 nodes x 4 float4 chunks
#pragma unroll
        for (int i = tid; i < 128 * 4; i += 256) {
            int nn = i & 127;
            int c  = i >> 7;            // 0..3 -> k offset c*4
            int node = node_base + nn;
            float4 v = make_float4(0.f, 0.f, 0.f, 0.f);
            if (node < n) {
                v = *reinterpret_cast<const float4*>(x1 + (size_t)node * K1 + kc + c * 4);
                if (ADD2) {
                    float4 u = *reinterpret_cast<const float4*>(x2 + (size_t)node * K1 + kc + c * 4);
                    v.x += u.x; v.y += u.y; v.z += u.z; v.w += u.w;
                }
            }
            Xs[(c * 4 + 0) * XP + nn] = v.x;
            Xs[(c * 4 + 1) * XP + nn] = v.y;
            Xs[(c * 4 + 2) * XP + nn] = v.z;
            Xs[(c * 4 + 3) * XP + nn] = v.w;
        }
        __syncthreads();

#pragma unroll
        for (int kk = 0; kk < 16; kk++) {
            float4 xv = *reinterpret_cast<const float4*>(Xs + kk * XP + tn * 4);
            const float* wrow = W1 + (kc + kk) * HD + tf * 8;
            ulonglong2 w01 = *reinterpret_cast<const ulonglong2*>(wrow);
            ulonglong2 w23 = *reinterpret_cast<const ulonglong2*>(wrow + 4);
            ull xd[4] = {pack_dup(xv.x), pack_dup(xv.y), pack_dup(xv.z), pack_dup(xv.w)};
#pragma unroll
            for (int i = 0; i < 4; i++) {
                fma2(acc[i][0], xd[i], w01.x);
                fma2(acc[i][1], xd[i], w01.y);
                fma2(acc[i][2], xd[i], w23.x);
                fma2(acc[i][3], xd[i], w23.y);
            }
        }
    }

    // phase-1 epilogue: relu -> As[feat][node] (transposed; STS.128 conflict-free)
    {
        float vals[4][8];
#pragma unroll
        for (int i = 0; i < 4; i++) {
#pragma unroll
            for (int j2 = 0; j2 < 4; j2++) {
                float2 p = unpack2(acc[i][j2]);
                vals[i][j2 * 2 + 0] = fmaxf(p.x, 0.f);
                vals[i][j2 * 2 + 1] = fmaxf(p.y, 0.f);
            }
        }
#pragma unroll
        for (int j = 0; j < 8; j++) {
            float4 v = make_float4(vals[0][j], vals[1][j], vals[2][j], vals[3][j]);
            *reinterpret_cast<float4*>(As + (tf * 8 + j) * XP + tn * 4) = v;
        }
    }
    __syncthreads();

    // ---------------- phase 2: a @ W2 ----------------
    {   // re-init with b2
        ulonglong2 b01 = *reinterpret_cast<const ulonglong2*>(b2 + tf * 8);
        ulonglong2 b23 = *reinterpret_cast<const ulonglong2*>(b2 + tf * 8 + 4);
#pragma unroll
        for (int i = 0; i < 4; i++) {
            acc[i][0] = b01.x; acc[i][1] = b01.y;
            acc[i][2] = b23.x; acc[i][3] = b23.y;
        }
    }

#pragma unroll 8
    for (int kk = 0; kk < HD; kk++) {
        float4 xv = *reinterpret_cast<const float4*>(As + kk * XP + tn * 4);
        const float* wrow = W2 + kk * HD + tf * 8;
        ulonglong2 w01 = *reinterpret_cast<const ulonglong2*>(wrow);
        ulonglong2 w23 = *reinterpret_cast<const ulonglong2*>(wrow + 4);
        ull xd[4] = {pack_dup(xv.x), pack_dup(xv.y), pack_dup(xv.z), pack_dup(xv.w)};
#pragma unroll
        for (int i = 0; i < 4; i++) {
            fma2(acc[i][0], xd[i], w01.x);
            fma2(acc[i][1], xd[i], w01.y);
            fma2(acc[i][2], xd[i], w23.x);
            fma2(acc[i][3], xd[i], w23.y);
        }
    }

    // phase-2 epilogue
#pragma unroll
    for (int i = 0; i < 4; i++) {
        int node = node_base + tn * 4 + i;
        if (node >= n) continue;
        float2 p0 = unpack2(acc[i][0]);
        float2 p1 = unpack2(acc[i][1]);
        float2 p2 = unpack2(acc[i][2]);
        float2 p3 = unpack2(acc[i][3]);
        float4 ra = make_float4(fmaxf(p0.x, 0.f), fmaxf(p0.y, 0.f),
                                fmaxf(p1.x, 0.f), fmaxf(p1.y, 0.f));
        float4 rb = make_float4(fmaxf(p2.x, 0.f), fmaxf(p2.y, 0.f),
                                fmaxf(p3.x, 0.f), fmaxf(p3.y, 0.f));
        if (!POOL) {
            float* o = out + (size_t)node * HD + tf * 8;
            *reinterpret_cast<float4*>(o)     = ra;
            *reinterpret_cast<float4*>(o + 4) = rb;
        } else {
            int g = gids[node];
            float* sg = sums + (size_t)g * HD + tf * 8;
            atomicAdd(reinterpret_cast<float4*>(sg),     ra);
            atomicAdd(reinterpret_cast<float4*>(sg + 4), rb);
            if (tf == 0) atomicAdd(&cnts[g], 1.0f);
        }
    }
}

// ---------------- scorer: out[g] = relu(mean_h @ sw1 + sb1) @ sw2 + sb2 -----
__global__ void scorer_kernel(const float* __restrict__ sums,
                              const float* __restrict__ cnts,
                              const float* __restrict__ sw1,
                              const float* __restrict__ sb1,
                              const float* __restrict__ sw2,
                              const float* __restrict__ sb2,
                              float* __restrict__ out)
{
    int g = blockIdx.x;
    int f = threadIdx.x;           // 64 threads
    float cnt = fmaxf(cnts[g], 1.0f);
    float inv = 1.0f / cnt;
    float acc = sb1[f];
    const float* sg = sums + (size_t)g * HD;
    for (int k = 0; k < HD; k++) acc += (sg[k] * inv) * sw1[k * HD + f];
    float hf = fmaxf(acc, 0.f) * sw2[f];

    __shared__ float red[HD];
    red[f] = hf;
    __syncthreads();
    if (f < 32) red[f] += red[f + 32];
    __syncthreads();
    if (f < 32) {
        float v = red[f];
#pragma unroll
        for (int off = 16; off > 0; off >>= 1)
            v += __shfl_down_sync(0xFFFFFFFFu, v, off);
        if (f == 0) out[g] = v + sb2[0];
    }
}

// ---------------- launcher --------------------------------------------------
extern "C" void kernel_launch(void* const* d_in, const int* in_sizes, int n_in,
                              void* d_out, int out_size)
{
    const int*   labels = (const int*)  d_in[0];
    const int*   src    = (const int*)  d_in[1];
    const int*   dst    = (const int*)  d_in[2];
    const int*   gids   = (const int*)  d_in[3];
    const float* emb    = (const float*)d_in[4];
    const float* w1_0   = (const float*)d_in[5];
    const float* b1_0   = (const float*)d_in[6];
    const float* w2_0   = (const float*)d_in[7];
    const float* b2_0   = (const float*)d_in[8];
    const float* w1_1   = (const float*)d_in[9];
    const float* b1_1   = (const float*)d_in[10];
    const float* w2_1   = (const float*)d_in[11];
    const float* b2_1   = (const float*)d_in[12];
    const float* sw1    = (const float*)d_in[13];
    const float* sb1    = (const float*)d_in[14];
    const float* sw2    = (const float*)d_in[15];
    const float* sb2    = (const float*)d_in[16];
    float* out = (float*)d_out;

    int N = in_sizes[0];
    int E = in_sizes[1];
    int G = out_size;
    int max_label = in_sizes[4] / LD - 1;

    if (N > NMAX) N = NMAX;
    if (E > EMAX) E = EMAX;
    if (G > GMAX) G = GMAX;

    float *h0, *ag0, *h1, *ag1, *sums, *cnts;
    cudaGetSymbolAddress((void**)&h0,   g_h0);
    cudaGetSymbolAddress((void**)&ag0,  g_ag0);
    cudaGetSymbolAddress((void**)&h1,   g_h1);
    cudaGetSymbolAddress((void**)&ag1,  g_ag1);
    cudaGetSymbolAddress((void**)&sums, g_sum);
    cudaGetSymbolAddress((void**)&cnts, g_cnt);

    const int TB = 256;
    const int NB = (N + 127) / 128;   // MLP node tiles

    // 1. embedding + zero accumulators
    init_kernel<<<(N * HD + TB - 1) / TB, TB>>>(labels, emb, N, G, max_label,
                                                h0, ag0, ag1, sums, cnts);
    // 2. layer0 scatter: ag0[dst] += h0[src]  (32-dim)
    scatter_kernel<LD><<<(E * (LD / 4) + TB - 1) / TB, TB>>>(src, dst, h0, ag0, E);
    // 3. layer0 fused MLP: h1 = relu(relu((h0+ag0)@w1_0+b1_0)@w2_0+b2_0)
    mlp2_kernel<LD, true, false><<<NB, 256>>>(h0, ag0, w1_0, b1_0, w2_0, b2_0,
                                              h1, nullptr, nullptr, nullptr, N);
    // 4. layer1 scatter: ag1[dst] += h1[src]  (64-dim)
    scatter_kernel<HD><<<(E * (HD / 4) + TB - 1) / TB, TB>>>(src, dst, h1, ag1, E);
    // 5. layer1 fused MLP + mean-pool accumulation
    mlp2_kernel<HD, true, true ><<<NB, 256>>>(h1, ag1, w1_1, b1_1, w2_1, b2_1,
                                              nullptr, gids, sums, cnts, N);
    // 6. scorer
    scorer_kernel<<<G, HD>>>(sums, cnts, sw1, sb1, sw2, sb2, out);
}

// round 10
// speedup vs baseline: 1.1324x; 1.0561x over previous
#include <cuda_runtime.h>
#include <cuda_bf16.h>

typedef unsigned long long ull;

// ---------------- problem constants (fixed shapes per reference) -------------
#define NMAX   50000
#define EMAX   1250000
#define GMAX   1024
#define LD     32      // label/embedding dim
#define HD     64      // hidden dim

// ---------------- device scratch (no allocation allowed) --------------------
__device__ float g_h0 [NMAX * LD];   // embedded labels
__device__ float g_ag0[NMAX * LD];   // layer0 aggregation
__device__ float g_h1 [NMAX * HD];   // layer0 output h
__device__ float g_ag1[NMAX * HD];   // layer1 aggregation
__device__ float g_sum[GMAX * HD];   // per-graph feature sums
__device__ float g_cnt[GMAX];        // per-graph node counts

// ---------------- packed f32x2 helpers (Blackwell FFMA2) --------------------
__device__ __forceinline__ void fma2(ull& acc, ull a, ull b) {
    asm("fma.rn.f32x2 %0, %1, %2, %0;" : "+l"(acc) : "l"(a), "l"(b));
}
__device__ __forceinline__ ull pack_dup(float x) {
    ull r;
    asm("mov.b64 %0, {%1, %1};" : "=l"(r) : "r"(__float_as_uint(x)));
    return r;
}
__device__ __forceinline__ float2 unpack2(ull v) {
    unsigned lo, hi;
    asm("mov.b64 {%0, %1}, %2;" : "=r"(lo), "=r"(hi) : "l"(v));
    return make_float2(__uint_as_float(lo), __uint_as_float(hi));
}

// ---------------- init: embedding lookup + zero all accumulators ------------
__global__ void init_kernel(const int* __restrict__ labels,
                            const float* __restrict__ emb,
                            int n, int g, int max_label,
                            float* __restrict__ h0, float* __restrict__ ag0,
                            float* __restrict__ ag1,
                            float* __restrict__ sums, float* __restrict__ cnts)
{
    int idx = blockIdx.x * blockDim.x + threadIdx.x;
    if (idx < n * LD) {
        int node = idx >> 5;
        int d    = idx & (LD - 1);
        int lab  = labels[node];
        lab = lab < 0 ? 0 : (lab > max_label ? max_label : lab);
        h0[idx]  = emb[lab * LD + d];
        ag0[idx] = 0.f;
    }
    if (idx < n * HD) ag1[idx] = 0.f;
    if (idx < g * HD) sums[idx] = 0.f;
    if (idx < g)      cnts[idx] = 0.f;
}

// ---------------- warp-cooperative edge scatter ------------------------------
// agg[dst] += h[src]. Each warp owns 32 edges: indices loaded coalesced once
// (2 LDGs/warp), then broadcast via shfl. Per sub-iter, 32/(DIM/4) edges are
// processed; each lane moves one float4 (LDG.128 + RED.128).
template <int DIM>
__global__ void __launch_bounds__(256)
scatter_kernel(const int* __restrict__ src,
               const int* __restrict__ dst,
               const float* __restrict__ h,
               float* __restrict__ agg, int E)
{
    const int LPE = DIM / 4;             // lanes per edge (16 or 8)
    const int EPW = 32 / LPE;            // edges per sub-iteration (2 or 4)
    int warp = (blockIdx.x * blockDim.x + threadIdx.x) >> 5;
    int lane = threadIdx.x & 31;
    int base = warp * 32;
    if (base >= E) return;

    int s = 0, d = 0;
    if (base + lane < E) {
        s = __ldg(&src[base + lane]);
        d = __ldg(&dst[base + lane]);
    }

    const int sub = lane / LPE;          // edge slot within sub-iter
    const int j4  = lane % LPE;          // float4 chunk within the row
    int m = E - base; if (m > 32) m = 32;

    if (m == 32) {
        // full warp fast path: compile-time trip count, fully unrolled
#pragma unroll
        for (int j = 0; j < 32; j += EPW) {
            int eidx = j + sub;
            int es = __shfl_sync(0xFFFFFFFFu, s, eidx);
            int ed = __shfl_sync(0xFFFFFFFFu, d, eidx);
            float4 v = *reinterpret_cast<const float4*>(h + (size_t)es * DIM + j4 * 4);
            atomicAdd(reinterpret_cast<float4*>(agg + (size_t)ed * DIM + j4 * 4), v);
        }
    } else {
        for (int j = 0; j < m; j += EPW) {
            int eidx = j + sub;
            int es = __shfl_sync(0xFFFFFFFFu, s, eidx & 31);
            int ed = __shfl_sync(0xFFFFFFFFu, d, eidx & 31);
            if (eidx < m) {
                float4 v = *reinterpret_cast<const float4*>(h + (size_t)es * DIM + j4 * 4);
                atomicAdd(reinterpret_cast<float4*>(agg + (size_t)ed * DIM + j4 * 4), v);
            }
        }
    }
}

// ---------------- fused 2-layer MLP (one GIN MLP) ----------------------------
// For a 128-node tile:
//   phase 1: a = relu((x1[+x2]) @ W1 + b1)   -> smem As (transposed [feat][node])
//   phase 2: y = relu(a @ W2 + b2)           -> global out, or pooled (POOL)
// 256 threads; thread = 4 nodes (lane-contiguous) x 8 feats, FFMA2 accumulators.
// W/bias read via uniform-address LDG.128 (warp broadcast, L1-resident).
template <int K1, bool ADD2, bool POOL>
__global__ void __launch_bounds__(256)
mlp2_kernel(const float* __restrict__ x1, const float* __restrict__ x2,
            const float* __restrict__ W1, const float* __restrict__ b1,
            const float* __restrict__ W2, const float* __restrict__ b2,
            float* __restrict__ out,
            const int* __restrict__ gids,
            float* __restrict__ sums, float* __restrict__ cnts, int n)
{
    const int XP = 132;                 // row pitch (floats)
    __shared__ float As[HD * XP];       // intermediate, transposed [k2][node]
    __shared__ float Xs[16 * XP];       // 16-k staging chunk of X, [k][node]

    const int tid = threadIdx.x;
    const int node_base = blockIdx.x * 128;
    const int tn = tid & 31;            // node group: 4 lane-contiguous nodes
    const int tf = tid >> 5;            // feature group: 8 feats = 4 f32x2

    ull acc[4][4];
    {   // init with b1
        ulonglong2 b01 = *reinterpret_cast<const ulonglong2*>(b1 + tf * 8);
        ulonglong2 b23 = *reinterpret_cast<const ulonglong2*>(b1 + tf * 8 + 4);
#pragma unroll
        for (int i = 0; i < 4; i++) {
            acc[i][0] = b01.x; acc[i][1] = b01.y;
            acc[i][2] = b23.x; acc[i][3] = b23.y;
        }
    }

    // ---------------- phase 1: x @ W1 ----------------
    for (int kc = 0; kc < K1; kc += 16) {
        if (kc > 0) __syncthreads();    // protect Xs reuse
#pragma unroll
        for (int i = tid; i < 128 * 4; i += 256) {
            int nn = i & 127;
            int c  = i >> 7;            // 0..3 -> k offset c*4
            int node = node_base + nn;
            float4 v = make_float4(0.f, 0.f, 0.f, 0.f);
            if (node < n) {
                v = *reinterpret_cast<const float4*>(x1 + (size_t)node * K1 + kc + c * 4);
                if (ADD2) {
                    float4 u = *reinterpret_cast<const float4*>(x2 + (size_t)node * K1 + kc + c * 4);
                    v.x += u.x; v.y += u.y; v.z += u.z; v.w += u.w;
                }
            }
            Xs[(c * 4 + 0) * XP + nn] = v.x;
            Xs[(c * 4 + 1) * XP + nn] = v.y;
            Xs[(c * 4 + 2) * XP + nn] = v.z;
            Xs[(c * 4 + 3) * XP + nn] = v.w;
        }
        __syncthreads();

#pragma unroll
        for (int kk = 0; kk < 16; kk++) {
            float4 xv = *reinterpret_cast<const float4*>(Xs + kk * XP + tn * 4);
            const float* wrow = W1 + (kc + kk) * HD + tf * 8;
            ulonglong2 w01 = *reinterpret_cast<const ulonglong2*>(wrow);
            ulonglong2 w23 = *reinterpret_cast<const ulonglong2*>(wrow + 4);
            ull xd[4] = {pack_dup(xv.x), pack_dup(xv.y), pack_dup(xv.z), pack_dup(xv.w)};
#pragma unroll
            for (int i = 0; i < 4; i++) {
                fma2(acc[i][0], xd[i], w01.x);
                fma2(acc[i][1], xd[i], w01.y);
                fma2(acc[i][2], xd[i], w23.x);
                fma2(acc[i][3], xd[i], w23.y);
            }
        }
    }

    // phase-1 epilogue: relu -> As[feat][node] (transposed; STS.128 conflict-free)
    {
        float vals[4][8];
#pragma unroll
        for (int i = 0; i < 4; i++) {
#pragma unroll
            for (int j2 = 0; j2 < 4; j2++) {
                float2 p = unpack2(acc[i][j2]);
                vals[i][j2 * 2 + 0] = fmaxf(p.x, 0.f);
                vals[i][j2 * 2 + 1] = fmaxf(p.y, 0.f);
            }
        }
#pragma unroll
        for (int j = 0; j < 8; j++) {
            float4 v = make_float4(vals[0][j], vals[1][j], vals[2][j], vals[3][j]);
            *reinterpret_cast<float4*>(As + (tf * 8 + j) * XP + tn * 4) = v;
        }
    }
    __syncthreads();

    // ---------------- phase 2: a @ W2 ----------------
    {   // re-init with b2
        ulonglong2 b01 = *reinterpret_cast<const ulonglong2*>(b2 + tf * 8);
        ulonglong2 b23 = *reinterpret_cast<const ulonglong2*>(b2 + tf * 8 + 4);
#pragma unroll
        for (int i = 0; i < 4; i++) {
            acc[i][0] = b01.x; acc[i][1] = b01.y;
            acc[i][2] = b23.x; acc[i][3] = b23.y;
        }
    }

#pragma unroll 8
    for (int kk = 0; kk < HD; kk++) {
        float4 xv = *reinterpret_cast<const float4*>(As + kk * XP + tn * 4);
        const float* wrow = W2 + kk * HD + tf * 8;
        ulonglong2 w01 = *reinterpret_cast<const ulonglong2*>(wrow);
        ulonglong2 w23 = *reinterpret_cast<const ulonglong2*>(wrow + 4);
        ull xd[4] = {pack_dup(xv.x), pack_dup(xv.y), pack_dup(xv.z), pack_dup(xv.w)};
#pragma unroll
        for (int i = 0; i < 4; i++) {
            fma2(acc[i][0], xd[i], w01.x);
            fma2(acc[i][1], xd[i], w01.y);
            fma2(acc[i][2], xd[i], w23.x);
            fma2(acc[i][3], xd[i], w23.y);
        }
    }

    // phase-2 epilogue
#pragma unroll
    for (int i = 0; i < 4; i++) {
        int node = node_base + tn * 4 + i;
        if (node >= n) continue;
        float2 p0 = unpack2(acc[i][0]);
        float2 p1 = unpack2(acc[i][1]);
        float2 p2 = unpack2(acc[i][2]);
        float2 p3 = unpack2(acc[i][3]);
        float4 ra = make_float4(fmaxf(p0.x, 0.f), fmaxf(p0.y, 0.f),
                                fmaxf(p1.x, 0.f), fmaxf(p1.y, 0.f));
        float4 rb = make_float4(fmaxf(p2.x, 0.f), fmaxf(p2.y, 0.f),
                                fmaxf(p3.x, 0.f), fmaxf(p3.y, 0.f));
        if (!POOL) {
            float* o = out + (size_t)node * HD + tf * 8;
            *reinterpret_cast<float4*>(o)     = ra;
            *reinterpret_cast<float4*>(o + 4) = rb;
        } else {
            int g = gids[node];
            float* sg = sums + (size_t)g * HD + tf * 8;
            atomicAdd(reinterpret_cast<float4*>(sg),     ra);
            atomicAdd(reinterpret_cast<float4*>(sg + 4), rb);
            if (tf == 0) atomicAdd(&cnts[g], 1.0f);
        }
    }
}

// ---------------- scorer: out[g] = relu(mean_h @ sw1 + sb1) @ sw2 + sb2 -----
__global__ void scorer_kernel(const float* __restrict__ sums,
                              const float* __restrict__ cnts,
                              const float* __restrict__ sw1,
                              const float* __restrict__ sb1,
                              const float* __restrict__ sw2,
                              const float* __restrict__ sb2,
                              float* __restrict__ out)
{
    int g = blockIdx.x;
    int f = threadIdx.x;           // 64 threads
    float cnt = fmaxf(cnts[g], 1.0f);
    float inv = 1.0f / cnt;
    float acc = sb1[f];
    const float* sg = sums + (size_t)g * HD;
    for (int k = 0; k < HD; k++) acc += (sg[k] * inv) * sw1[k * HD + f];
    float hf = fmaxf(acc, 0.f) * sw2[f];

    __shared__ float red[HD];
    red[f] = hf;
    __syncthreads();
    if (f < 32) red[f] += red[f + 32];
    __syncthreads();
    if (f < 32) {
        float v = red[f];
#pragma unroll
        for (int off = 16; off > 0; off >>= 1)
            v += __shfl_down_sync(0xFFFFFFFFu, v, off);
        if (f == 0) out[g] = v + sb2[0];
    }
}

// ---------------- launcher --------------------------------------------------
extern "C" void kernel_launch(void* const* d_in, const int* in_sizes, int n_in,
                              void* d_out, int out_size)
{
    const int*   labels = (const int*)  d_in[0];
    const int*   src    = (const int*)  d_in[1];
    const int*   dst    = (const int*)  d_in[2];
    const int*   gids   = (const int*)  d_in[3];
    const float* emb    = (const float*)d_in[4];
    const float* w1_0   = (const float*)d_in[5];
    const float* b1_0   = (const float*)d_in[6];
    const float* w2_0   = (const float*)d_in[7];
    const float* b2_0   = (const float*)d_in[8];
    const float* w1_1   = (const float*)d_in[9];
    const float* b1_1   = (const float*)d_in[10];
    const float* w2_1   = (const float*)d_in[11];
    const float* b2_1   = (const float*)d_in[12];
    const float* sw1    = (const float*)d_in[13];
    const float* sb1    = (const float*)d_in[14];
    const float* sw2    = (const float*)d_in[15];
    const float* sb2    = (const float*)d_in[16];
    float* out = (float*)d_out;

    int N = in_sizes[0];
    int E = in_sizes[1];
    int G = out_size;
    int max_label = in_sizes[4] / LD - 1;

    if (N > NMAX) N = NMAX;
    if (E > EMAX) E = EMAX;
    if (G > GMAX) G = GMAX;

    float *h0, *ag0, *h1, *ag1, *sums, *cnts;
    cudaGetSymbolAddress((void**)&h0,   g_h0);
    cudaGetSymbolAddress((void**)&ag0,  g_ag0);
    cudaGetSymbolAddress((void**)&h1,   g_h1);
    cudaGetSymbolAddress((void**)&ag1,  g_ag1);
    cudaGetSymbolAddress((void**)&sums, g_sum);
    cudaGetSymbolAddress((void**)&cnts, g_cnt);

    const int TB = 256;
    const int NB = (N + 127) / 128;                 // MLP node tiles
    const int SB = ((E + 31) / 32 + 7) / 8;         // scatter blocks (8 warps each)

    // 1. embedding + zero accumulators
    init_kernel<<<(N * HD + TB - 1) / TB, TB>>>(labels, emb, N, G, max_label,
                                                h0, ag0, ag1, sums, cnts);
    // 2. layer0 scatter: ag0[dst] += h0[src]  (32-dim)
    scatter_kernel<LD><<<SB, TB>>>(src, dst, h0, ag0, E);
    // 3. layer0 fused MLP: h1 = relu(relu((h0+ag0)@w1_0+b1_0)@w2_0+b2_0)
    mlp2_kernel<LD, true, false><<<NB, 256>>>(h0, ag0, w1_0, b1_0, w2_0, b2_0,
                                              h1, nullptr, nullptr, nullptr, N);
    // 4. layer1 scatter: ag1[dst] += h1[src]  (64-dim)
    scatter_kernel<HD><<<SB, TB>>>(src, dst, h1, ag1, E);
    // 5. layer1 fused MLP + mean-pool accumulation
    mlp2_kernel<HD, true, true ><<<NB, 256>>>(h1, ag1, w1_1, b1_1, w2_1, b2_1,
                                              nullptr, gids, sums, cnts, N);
    // 6. scorer
    scorer_kernel<<<G, HD>>>(sums, cnts, sw1, sb1, sw2, sb2, out);
}

// round 11
// speedup vs baseline: 1.1830x; 1.0447x over previous
#include <cuda_runtime.h>
#include <cuda_bf16.h>

typedef unsigned long long ull;
typedef unsigned int u32;

// ---------------- problem constants (fixed shapes per reference) -------------
#define NMAX   50000
#define EMAX   1250000
#define GMAX   1024
#define LD     32      // label/embedding dim
#define HD     64      // hidden dim
#define NL     51      // number of labels (MAX_LABEL+1)
#define CW     32      // packed u16 count words per node (64 halves >= NL)

// ---------------- device scratch (no allocation allowed) --------------------
__device__ u32   g_lcnt[NMAX * CW];  // per-node packed u16 label histograms
__device__ float g_EW  [NL * HD];    // emb @ W1_0  (51 x 64)
__device__ float g_h1 [NMAX * HD];   // layer0 output h
__device__ float g_ag1[NMAX * HD];   // layer1 aggregation
__device__ float g_sum[GMAX * HD];   // per-graph feature sums
__device__ float g_cnt[GMAX];        // per-graph node counts

// ---------------- packed f32x2 helpers (Blackwell FFMA2) --------------------
__device__ __forceinline__ void fma2(ull& acc, ull a, ull b) {
    asm("fma.rn.f32x2 %0, %1, %2, %0;" : "+l"(acc) : "l"(a), "l"(b));
}
__device__ __forceinline__ ull pack_dup(float x) {
    ull r;
    asm("mov.b64 %0, {%1, %1};" : "=l"(r) : "r"(__float_as_uint(x)));
    return r;
}
__device__ __forceinline__ float2 unpack2(ull v) {
    unsigned lo, hi;
    asm("mov.b64 {%0, %1}, %2;" : "=r"(lo), "=r"(hi) : "l"(v));
    return make_float2(__uint_as_float(lo), __uint_as_float(hi));
}

// ---------------- init: zero accumulators, seed self-label counts ------------
__global__ void init_kernel(const int* __restrict__ labels, int n, int g,
                            u32* __restrict__ lcnt,
                            float* __restrict__ ag1,
                            float* __restrict__ sums, float* __restrict__ cnts)
{
    int idx = blockIdx.x * blockDim.x + threadIdx.x;
    if (idx < n) {
        // zero this node's 32 count words, then set self label = 1
        uint4 z = make_uint4(0, 0, 0, 0);
        uint4* p = reinterpret_cast<uint4*>(lcnt + (size_t)idx * CW);
#pragma unroll
        for (int w = 0; w < CW / 4; w++) p[w] = z;
        int lab = labels[idx];
        lab = lab < 0 ? 0 : (lab > NL - 1 ? NL - 1 : lab);
        lcnt[(size_t)idx * CW + (lab >> 1)] = 1u << ((lab & 1) * 16);
    }
    if (idx < n * HD) ag1[idx] = 0.f;
    if (idx < g * HD) sums[idx] = 0.f;
    if (idx < g)      cnts[idx] = 0.f;
}

// ---------------- EW = emb @ W1_0  (51 x 64, tiny) ---------------------------
__global__ void ew_kernel(const float* __restrict__ emb,
                          const float* __restrict__ W1,
                          float* __restrict__ EW)
{
    int idx = blockIdx.x * blockDim.x + threadIdx.x;
    if (idx >= NL * HD) return;
    int l = idx / HD, f = idx % HD;
    float s = 0.f;
#pragma unroll
    for (int k = 0; k < LD; k++) s += emb[l * LD + k] * W1[k * HD + f];
    EW[idx] = s;
}

// ---------------- layer0 edge pass: label histogram scatter ------------------
// lcnt[dst] half-word[label(src)] += 1  (one 4B atomic per edge)
__global__ void __launch_bounds__(256)
label_scatter_kernel(const int* __restrict__ src, const int* __restrict__ dst,
                     const int* __restrict__ labels, u32* __restrict__ lcnt, int E)
{
    int e = blockIdx.x * blockDim.x + threadIdx.x;
    if (e >= E) return;
    int s = __ldg(&src[e]);
    int d = __ldg(&dst[e]);
    int lab = __ldg(&labels[s]);
    lab = lab < 0 ? 0 : (lab > NL - 1 ? NL - 1 : lab);
    atomicAdd(&lcnt[(size_t)d * CW + (lab >> 1)], 1u << ((lab & 1) * 16));
}

// ---------------- layer0 fused MLP from label counts -------------------------
// phase 1: a = relu(b1 + cnt' @ EW)    (K = 51, counts staged as floats)
// phase 2: h1 = relu(a @ W2 + b2)
// 256 threads; thread = 4 nodes x 8 feats, FFMA2 accumulators.
// Dynamic smem: As[HD][132] + Cs[52][132] floats.
#define XP   132
#define CROWS 52
#define SMEM0_BYTES ((HD + CROWS) * XP * 4)
__global__ void __launch_bounds__(256)
mlp0_kernel(const u32* __restrict__ lcnt,
            const float* __restrict__ EW, const float* __restrict__ b1,
            const float* __restrict__ W2, const float* __restrict__ b2,
            float* __restrict__ out, int n)
{
    extern __shared__ float smem[];
    float* As = smem;                 // [HD][XP]
    float* Cs = smem + HD * XP;       // [CROWS][XP]

    const int tid = threadIdx.x;
    const int node_base = blockIdx.x * 128;
    const int tn = tid & 31;
    const int tf = tid >> 5;

    // stage counts -> Cs[label][node] as floats (words 0..27 cover labels 0..55)
#pragma unroll
    for (int i = tid; i < 128 * 7; i += 256) {
        int nn = i & 127;
        int c  = i >> 7;              // word group 0..6 -> labels c*8 .. c*8+7
        int node = node_base + nn;
        uint4 w = make_uint4(0, 0, 0, 0);
        if (node < n)
            w = *reinterpret_cast<const uint4*>(lcnt + (size_t)node * CW + c * 4);
        u32 ws[4] = {w.x, w.y, w.z, w.w};
#pragma unroll
        for (int j = 0; j < 4; j++) {
            int l0 = c * 8 + j * 2;
            if (l0 < CROWS)     Cs[l0 * XP + nn]       = (float)(ws[j] & 0xFFFFu);
            if (l0 + 1 < CROWS) Cs[(l0 + 1) * XP + nn] = (float)(ws[j] >> 16);
        }
    }
    __syncthreads();

    ull acc[4][4];
    {   // init with b1
        ulonglong2 b01 = *reinterpret_cast<const ulonglong2*>(b1 + tf * 8);
        ulonglong2 b23 = *reinterpret_cast<const ulonglong2*>(b1 + tf * 8 + 4);
#pragma unroll
        for (int i = 0; i < 4; i++) {
            acc[i][0] = b01.x; acc[i][1] = b01.y;
            acc[i][2] = b23.x; acc[i][3] = b23.y;
        }
    }

    // ---------------- phase 1: cnt' @ EW  (51 iterations) ----------------
#pragma unroll 3
    for (int l = 0; l < NL; l++) {
        float4 xv = *reinterpret_cast<const float4*>(Cs + l * XP + tn * 4);
        const float* wrow = EW + l * HD + tf * 8;
        ulonglong2 w01 = *reinterpret_cast<const ulonglong2*>(wrow);
        ulonglong2 w23 = *reinterpret_cast<const ulonglong2*>(wrow + 4);
        ull xd[4] = {pack_dup(xv.x), pack_dup(xv.y), pack_dup(xv.z), pack_dup(xv.w)};
#pragma unroll
        for (int i = 0; i < 4; i++) {
            fma2(acc[i][0], xd[i], w01.x);
            fma2(acc[i][1], xd[i], w01.y);
            fma2(acc[i][2], xd[i], w23.x);
            fma2(acc[i][3], xd[i], w23.y);
        }
    }

    // phase-1 epilogue: relu -> As[feat][node]
    {
        float vals[4][8];
#pragma unroll
        for (int i = 0; i < 4; i++) {
#pragma unroll
            for (int j2 = 0; j2 < 4; j2++) {
                float2 p = unpack2(acc[i][j2]);
                vals[i][j2 * 2 + 0] = fmaxf(p.x, 0.f);
                vals[i][j2 * 2 + 1] = fmaxf(p.y, 0.f);
            }
        }
#pragma unroll
        for (int j = 0; j < 8; j++) {
            float4 v = make_float4(vals[0][j], vals[1][j], vals[2][j], vals[3][j]);
            *reinterpret_cast<float4*>(As + (tf * 8 + j) * XP + tn * 4) = v;
        }
    }
    __syncthreads();

    // ---------------- phase 2: a @ W2 ----------------
    {
        ulonglong2 b01 = *reinterpret_cast<const ulonglong2*>(b2 + tf * 8);
        ulonglong2 b23 = *reinterpret_cast<const ulonglong2*>(b2 + tf * 8 + 4);
#pragma unroll
        for (int i = 0; i < 4; i++) {
            acc[i][0] = b01.x; acc[i][1] = b01.y;
            acc[i][2] = b23.x; acc[i][3] = b23.y;
        }
    }

#pragma unroll 8
    for (int kk = 0; kk < HD; kk++) {
        float4 xv = *reinterpret_cast<const float4*>(As + kk * XP + tn * 4);
        const float* wrow = W2 + kk * HD + tf * 8;
        ulonglong2 w01 = *reinterpret_cast<const ulonglong2*>(wrow);
        ulonglong2 w23 = *reinterpret_cast<const ulonglong2*>(wrow + 4);
        ull xd[4] = {pack_dup(xv.x), pack_dup(xv.y), pack_dup(xv.z), pack_dup(xv.w)};
#pragma unroll
        for (int i = 0; i < 4; i++) {
            fma2(acc[i][0], xd[i], w01.x);
            fma2(acc[i][1], xd[i], w01.y);
            fma2(acc[i][2], xd[i], w23.x);
            fma2(acc[i][3], xd[i], w23.y);
        }
    }

#pragma unroll
    for (int i = 0; i < 4; i++) {
        int node = node_base + tn * 4 + i;
        if (node >= n) continue;
        float2 p0 = unpack2(acc[i][0]);
        float2 p1 = unpack2(acc[i][1]);
        float2 p2 = unpack2(acc[i][2]);
        float2 p3 = unpack2(acc[i][3]);
        float* o = out + (size_t)node * HD + tf * 8;
        *reinterpret_cast<float4*>(o) =
            make_float4(fmaxf(p0.x, 0.f), fmaxf(p0.y, 0.f),
                        fmaxf(p1.x, 0.f), fmaxf(p1.y, 0.f));
        *reinterpret_cast<float4*>(o + 4) =
            make_float4(fmaxf(p2.x, 0.f), fmaxf(p2.y, 0.f),
                        fmaxf(p3.x, 0.f), fmaxf(p3.y, 0.f));
    }
}

// ---------------- warp-cooperative edge scatter (layer1, 64-dim) -------------
template <int DIM>
__global__ void __launch_bounds__(256)
scatter_kernel(const int* __restrict__ src,
               const int* __restrict__ dst,
               const float* __restrict__ h,
               float* __restrict__ agg, int E)
{
    const int LPE = DIM / 4;
    const int EPW = 32 / LPE;
    int warp = (blockIdx.x * blockDim.x + threadIdx.x) >> 5;
    int lane = threadIdx.x & 31;
    int base = warp * 32;
    if (base >= E) return;

    int s = 0, d = 0;
    if (base + lane < E) {
        s = __ldg(&src[base + lane]);
        d = __ldg(&dst[base + lane]);
    }

    const int sub = lane / LPE;
    const int j4  = lane % LPE;
    int m = E - base; if (m > 32) m = 32;

    if (m == 32) {
#pragma unroll
        for (int j = 0; j < 32; j += EPW) {
            int eidx = j + sub;
            int es = __shfl_sync(0xFFFFFFFFu, s, eidx);
            int ed = __shfl_sync(0xFFFFFFFFu, d, eidx);
            float4 v = *reinterpret_cast<const float4*>(h + (size_t)es * DIM + j4 * 4);
            atomicAdd(reinterpret_cast<float4*>(agg + (size_t)ed * DIM + j4 * 4), v);
        }
    } else {
        for (int j = 0; j < m; j += EPW) {
            int eidx = j + sub;
            int es = __shfl_sync(0xFFFFFFFFu, s, eidx & 31);
            int ed = __shfl_sync(0xFFFFFFFFu, d, eidx & 31);
            if (eidx < m) {
                float4 v = *reinterpret_cast<const float4*>(h + (size_t)es * DIM + j4 * 4);
                atomicAdd(reinterpret_cast<float4*>(agg + (size_t)ed * DIM + j4 * 4), v);
            }
        }
    }
}

// ---------------- fused 2-layer MLP (layer1) + mean-pool ---------------------
template <int K1>
__global__ void __launch_bounds__(256)
mlp2_kernel(const float* __restrict__ x1, const float* __restrict__ x2,
            const float* __restrict__ W1, const float* __restrict__ b1,
            const float* __restrict__ W2, const float* __restrict__ b2,
            const int* __restrict__ gids,
            float* __restrict__ sums, float* __restrict__ cnts, int n)
{
    __shared__ float As[HD * XP];
    __shared__ float Xs[16 * XP];

    const int tid = threadIdx.x;
    const int node_base = blockIdx.x * 128;
    const int tn = tid & 31;
    const int tf = tid >> 5;

    ull acc[4][4];
    {
        ulonglong2 b01 = *reinterpret_cast<const ulonglong2*>(b1 + tf * 8);
        ulonglong2 b23 = *reinterpret_cast<const ulonglong2*>(b1 + tf * 8 + 4);
#pragma unroll
        for (int i = 0; i < 4; i++) {
            acc[i][0] = b01.x; acc[i][1] = b01.y;
            acc[i][2] = b23.x; acc[i][3] = b23.y;
        }
    }

    for (int kc = 0; kc < K1; kc += 16) {
        if (kc > 0) __syncthreads();
#pragma unroll
        for (int i = tid; i < 128 * 4; i += 256) {
            int nn = i & 127;
            int c  = i >> 7;
            int node = node_base + nn;
            float4 v = make_float4(0.f, 0.f, 0.f, 0.f);
            if (node < n) {
                v = *reinterpret_cast<const float4*>(x1 + (size_t)node * K1 + kc + c * 4);
                float4 u = *reinterpret_cast<const float4*>(x2 + (size_t)node * K1 + kc + c * 4);
                v.x += u.x; v.y += u.y; v.z += u.z; v.w += u.w;
            }
            Xs[(c * 4 + 0) * XP + nn] = v.x;
            Xs[(c * 4 + 1) * XP + nn] = v.y;
            Xs[(c * 4 + 2) * XP + nn] = v.z;
            Xs[(c * 4 + 3) * XP + nn] = v.w;
        }
        __syncthreads();

#pragma unroll
        for (int kk = 0; kk < 16; kk++) {
            float4 xv = *reinterpret_cast<const float4*>(Xs + kk * XP + tn * 4);
            const float* wrow = W1 + (kc + kk) * HD + tf * 8;
            ulonglong2 w01 = *reinterpret_cast<const ulonglong2*>(wrow);
            ulonglong2 w23 = *reinterpret_cast<const ulonglong2*>(wrow + 4);
            ull xd[4] = {pack_dup(xv.x), pack_dup(xv.y), pack_dup(xv.z), pack_dup(xv.w)};
#pragma unroll
            for (int i = 0; i < 4; i++) {
                fma2(acc[i][0], xd[i], w01.x);
                fma2(acc[i][1], xd[i], w01.y);
                fma2(acc[i][2], xd[i], w23.x);
                fma2(acc[i][3], xd[i], w23.y);
            }
        }
    }

    {
        float vals[4][8];
#pragma unroll
        for (int i = 0; i < 4; i++) {
#pragma unroll
            for (int j2 = 0; j2 < 4; j2++) {
                float2 p = unpack2(acc[i][j2]);
                vals[i][j2 * 2 + 0] = fmaxf(p.x, 0.f);
                vals[i][j2 * 2 + 1] = fmaxf(p.y, 0.f);
            }
        }
#pragma unroll
        for (int j = 0; j < 8; j++) {
            float4 v = make_float4(vals[0][j], vals[1][j], vals[2][j], vals[3][j]);
            *reinterpret_cast<float4*>(As + (tf * 8 + j) * XP + tn * 4) = v;
        }
    }
    __syncthreads();

    {
        ulonglong2 b01 = *reinterpret_cast<const ulonglong2*>(b2 + tf * 8);
        ulonglong2 b23 = *reinterpret_cast<const ulonglong2*>(b2 + tf * 8 + 4);
#pragma unroll
        for (int i = 0; i < 4; i++) {
            acc[i][0] = b01.x; acc[i][1] = b01.y;
            acc[i][2] = b23.x; acc[i][3] = b23.y;
        }
    }

#pragma unroll 8
    for (int kk = 0; kk < HD; kk++) {
        float4 xv = *reinterpret_cast<const float4*>(As + kk * XP + tn * 4);
        const float* wrow = W2 + kk * HD + tf * 8;
        ulonglong2 w01 = *reinterpret_cast<const ulonglong2*>(wrow);
        ulonglong2 w23 = *reinterpret_cast<const ulonglong2*>(wrow + 4);
        ull xd[4] = {pack_dup(xv.x), pack_dup(xv.y), pack_dup(xv.z), pack_dup(xv.w)};
#pragma unroll
        for (int i = 0; i < 4; i++) {
            fma2(acc[i][0], xd[i], w01.x);
            fma2(acc[i][1], xd[i], w01.y);
            fma2(acc[i][2], xd[i], w23.x);
            fma2(acc[i][3], xd[i], w23.y);
        }
    }

#pragma unroll
    for (int i = 0; i < 4; i++) {
        int node = node_base + tn * 4 + i;
        if (node >= n) continue;
        float2 p0 = unpack2(acc[i][0]);
        float2 p1 = unpack2(acc[i][1]);
        float2 p2 = unpack2(acc[i][2]);
        float2 p3 = unpack2(acc[i][3]);
        float4 ra = make_float4(fmaxf(p0.x, 0.f), fmaxf(p0.y, 0.f),
                                fmaxf(p1.x, 0.f), fmaxf(p1.y, 0.f));
        float4 rb = make_float4(fmaxf(p2.x, 0.f), fmaxf(p2.y, 0.f),
                                fmaxf(p3.x, 0.f), fmaxf(p3.y, 0.f));
        int g = gids[node];
        float* sg = sums + (size_t)g * HD + tf * 8;
        atomicAdd(reinterpret_cast<float4*>(sg),     ra);
        atomicAdd(reinterpret_cast<float4*>(sg + 4), rb);
        if (tf == 0) atomicAdd(&cnts[g], 1.0f);
    }
}

// ---------------- scorer: out[g] = relu(mean_h @ sw1 + sb1) @ sw2 + sb2 -----
__global__ void scorer_kernel(const float* __restrict__ sums,
                              const float* __restrict__ cnts,
                              const float* __restrict__ sw1,
                              const float* __restrict__ sb1,
                              const float* __restrict__ sw2,
                              const float* __restrict__ sb2,
                              float* __restrict__ out)
{
    int g = blockIdx.x;
    int f = threadIdx.x;           // 64 threads
    float cnt = fmaxf(cnts[g], 1.0f);
    float inv = 1.0f / cnt;
    float acc = sb1[f];
    const float* sg = sums + (size_t)g * HD;
    for (int k = 0; k < HD; k++) acc += (sg[k] * inv) * sw1[k * HD + f];
    float hf = fmaxf(acc, 0.f) * sw2[f];

    __shared__ float red[HD];
    red[f] = hf;
    __syncthreads();
    if (f < 32) red[f] += red[f + 32];
    __syncthreads();
    if (f < 32) {
        float v = red[f];
#pragma unroll
        for (int off = 16; off > 0; off >>= 1)
            v += __shfl_down_sync(0xFFFFFFFFu, v, off);
        if (f == 0) out[g] = v + sb2[0];
    }
}

// ---------------- launcher --------------------------------------------------
extern "C" void kernel_launch(void* const* d_in, const int* in_sizes, int n_in,
                              void* d_out, int out_size)
{
    const int*   labels = (const int*)  d_in[0];
    const int*   src    = (const int*)  d_in[1];
    const int*   dst    = (const int*)  d_in[2];
    const int*   gids   = (const int*)  d_in[3];
    const float* emb    = (const float*)d_in[4];
    const float* w1_0   = (const float*)d_in[5];
    const float* b1_0   = (const float*)d_in[6];
    const float* w2_0   = (const float*)d_in[7];
    const float* b2_0   = (const float*)d_in[8];
    const float* w1_1   = (const float*)d_in[9];
    const float* b1_1   = (const float*)d_in[10];
    const float* w2_1   = (const float*)d_in[11];
    const float* b2_1   = (const float*)d_in[12];
    const float* sw1    = (const float*)d_in[13];
    const float* sb1    = (const float*)d_in[14];
    const float* sw2    = (const float*)d_in[15];
    const float* sb2    = (const float*)d_in[16];
    float* out = (float*)d_out;

    int N = in_sizes[0];
    int E = in_sizes[1];
    int G = out_size;

    if (N > NMAX) N = NMAX;
    if (E > EMAX) E = EMAX;
    if (G > GMAX) G = GMAX;

    u32 *lcnt;
    float *EW, *h1, *ag1, *sums, *cnts;
    cudaGetSymbolAddress((void**)&lcnt, g_lcnt);
    cudaGetSymbolAddress((void**)&EW,   g_EW);
    cudaGetSymbolAddress((void**)&h1,   g_h1);
    cudaGetSymbolAddress((void**)&ag1,  g_ag1);
    cudaGetSymbolAddress((void**)&sums, g_sum);
    cudaGetSymbolAddress((void**)&cnts, g_cnt);

    static bool attr_set = false;
    if (!attr_set) {
        cudaFuncSetAttribute(mlp0_kernel,
                             cudaFuncAttributeMaxDynamicSharedMemorySize,
                             SMEM0_BYTES);
        attr_set = true;
    }

    const int TB = 256;
    const int NB = (N + 127) / 128;                 // MLP node tiles
    const int SB = ((E + 31) / 32 + 7) / 8;         // scatter blocks (8 warps)

    // 1. zero accumulators + seed self-label counts; EW = emb @ W1_0
    init_kernel<<<(N * HD + TB - 1) / TB, TB>>>(labels, N, G, lcnt, ag1, sums, cnts);
    ew_kernel<<<(NL * HD + TB - 1) / TB, TB>>>(emb, w1_0, EW);
    // 2. layer0: label-histogram scatter (1 x 4B atomic per edge)
    label_scatter_kernel<<<(E + TB - 1) / TB, TB>>>(src, dst, labels, lcnt, E);
    // 3. layer0 fused MLP from counts: h1 = relu(relu(cnt'@EW + b1)@W2 + b2)
    mlp0_kernel<<<NB, 256, SMEM0_BYTES>>>(lcnt, EW, b1_0, w2_0, b2_0, h1, N);
    // 4. layer1 scatter: ag1[dst] += h1[src]  (64-dim, warp-cooperative)
    scatter_kernel<HD><<<SB, TB>>>(src, dst, h1, ag1, E);
    // 5. layer1 fused MLP + mean-pool accumulation
    mlp2_kernel<HD><<<NB, 256>>>(h1, ag1, w1_1, b1_1, w2_1, b2_1,
                                 gids, sums, cnts, N);
    // 6. scorer
    scorer_kernel<<<G, HD>>>(sums, cnts, sw1, sb1, sw2, sb2, out);
}

// round 12
// speedup vs baseline: 1.1867x; 1.0031x over previous
#include <cuda_runtime.h>
#include <cuda_bf16.h>

typedef unsigned long long ull;
typedef unsigned int u32;

// ---------------- problem constants (fixed shapes per reference) -------------
#define NMAX   50000
#define EMAX   1250000
#define GMAX   1024
#define LD     32      // label/embedding dim
#define HD     64      // hidden dim
#define NL     51      // number of labels (MAX_LABEL+1)
#define CW     32      // packed u16 count words per node (64 halves >= NL)

// ---------------- device scratch (no allocation allowed) --------------------
__device__ u32   g_lcnt[NMAX * CW];  // per-node packed u16 label histograms
__device__ float g_EW  [NL * HD];    // emb @ W1_0  (51 x 64)
__device__ float g_h1 [NMAX * HD];   // layer0 output h
__device__ float g_ag1[NMAX * HD];   // layer1 aggregation
__device__ float g_sum[GMAX * HD];   // per-graph feature sums
__device__ float g_cnt[GMAX];        // per-graph node counts

// ---------------- packed f32x2 helpers (Blackwell FFMA2) --------------------
__device__ __forceinline__ void fma2(ull& acc, ull a, ull b) {
    asm("fma.rn.f32x2 %0, %1, %2, %0;" : "+l"(acc) : "l"(a), "l"(b));
}
__device__ __forceinline__ ull pack_dup(float x) {
    ull r;
    asm("mov.b64 %0, {%1, %1};" : "=l"(r) : "r"(__float_as_uint(x)));
    return r;
}
__device__ __forceinline__ float2 unpack2(ull v) {
    unsigned lo, hi;
    asm("mov.b64 {%0, %1}, %2;" : "=r"(lo), "=r"(hi) : "l"(v));
    return make_float2(__uint_as_float(lo), __uint_as_float(hi));
}

// ---------------- init: zero accumulators, seed self-label counts ------------
__global__ void init_kernel(const int* __restrict__ labels, int n, int g,
                            u32* __restrict__ lcnt,
                            float* __restrict__ ag1,
                            float* __restrict__ sums, float* __restrict__ cnts)
{
    int idx = blockIdx.x * blockDim.x + threadIdx.x;
    if (idx < n) {
        // zero this node's 32 count words, then set self label = 1
        uint4 z = make_uint4(0, 0, 0, 0);
        uint4* p = reinterpret_cast<uint4*>(lcnt + (size_t)idx * CW);
#pragma unroll
        for (int w = 0; w < CW / 4; w++) p[w] = z;
        int lab = labels[idx];
        lab = lab < 0 ? 0 : (lab > NL - 1 ? NL - 1 : lab);
        lcnt[(size_t)idx * CW + (lab >> 1)] = 1u << ((lab & 1) * 16);
    }
    if (idx < n * HD) ag1[idx] = 0.f;
    if (idx < g * HD) sums[idx] = 0.f;
    if (idx < g)      cnts[idx] = 0.f;
}

// ---------------- EW = emb @ W1_0  (51 x 64, tiny) ---------------------------
__global__ void ew_kernel(const float* __restrict__ emb,
                          const float* __restrict__ W1,
                          float* __restrict__ EW)
{
    int idx = blockIdx.x * blockDim.x + threadIdx.x;
    if (idx >= NL * HD) return;
    int l = idx / HD, f = idx % HD;
    float s = 0.f;
#pragma unroll
    for (int k = 0; k < LD; k++) s += emb[l * LD + k] * W1[k * HD + f];
    EW[idx] = s;
}

// ---------------- layer0 edge pass: label histogram scatter ------------------
// lcnt[dst] half-word[label(src)] += 1  (one 4B atomic per edge)
__global__ void __launch_bounds__(256)
label_scatter_kernel(const int* __restrict__ src, const int* __restrict__ dst,
                     const int* __restrict__ labels, u32* __restrict__ lcnt, int E)
{
    int e = blockIdx.x * blockDim.x + threadIdx.x;
    if (e >= E) return;
    int s = __ldg(&src[e]);
    int d = __ldg(&dst[e]);
    int lab = __ldg(&labels[s]);
    lab = lab < 0 ? 0 : (lab > NL - 1 ? NL - 1 : lab);
    atomicAdd(&lcnt[(size_t)d * CW + (lab >> 1)], 1u << ((lab & 1) * 16));
}

// ---------------- layer0 fused MLP from label counts -------------------------
// phase 1: a = relu(b1 + cnt' @ EW)    (K = 51, counts staged as floats)
// phase 2: h1 = relu(a @ W2 + b2)
// 256 threads; thread = 4 nodes x 8 feats, FFMA2 accumulators.
// Dynamic smem: As[HD][132] + Cs[52][132] floats.
#define XP   132
#define CROWS 52
#define SMEM0_BYTES ((HD + CROWS) * XP * 4)
__global__ void __launch_bounds__(256)
mlp0_kernel(const u32* __restrict__ lcnt,
            const float* __restrict__ EW, const float* __restrict__ b1,
            const float* __restrict__ W2, const float* __restrict__ b2,
            float* __restrict__ out, int n)
{
    extern __shared__ float smem[];
    float* As = smem;                 // [HD][XP]
    float* Cs = smem + HD * XP;       // [CROWS][XP]

    const int tid = threadIdx.x;
    const int node_base = blockIdx.x * 128;
    const int tn = tid & 31;
    const int tf = tid >> 5;

    // stage counts -> Cs[label][node] as floats (words 0..27 cover labels 0..55)
#pragma unroll
    for (int i = tid; i < 128 * 7; i += 256) {
        int nn = i & 127;
        int c  = i >> 7;              // word group 0..6 -> labels c*8 .. c*8+7
        int node = node_base + nn;
        uint4 w = make_uint4(0, 0, 0, 0);
        if (node < n)
            w = *reinterpret_cast<const uint4*>(lcnt + (size_t)node * CW + c * 4);
        u32 ws[4] = {w.x, w.y, w.z, w.w};
#pragma unroll
        for (int j = 0; j < 4; j++) {
            int l0 = c * 8 + j * 2;
            if (l0 < CROWS)     Cs[l0 * XP + nn]       = (float)(ws[j] & 0xFFFFu);
            if (l0 + 1 < CROWS) Cs[(l0 + 1) * XP + nn] = (float)(ws[j] >> 16);
        }
    }
    __syncthreads();

    ull acc[4][4];
    {   // init with b1
        ulonglong2 b01 = *reinterpret_cast<const ulonglong2*>(b1 + tf * 8);
        ulonglong2 b23 = *reinterpret_cast<const ulonglong2*>(b1 + tf * 8 + 4);
#pragma unroll
        for (int i = 0; i < 4; i++) {
            acc[i][0] = b01.x; acc[i][1] = b01.y;
            acc[i][2] = b23.x; acc[i][3] = b23.y;
        }
    }

    // ---------------- phase 1: cnt' @ EW  (51 iterations) ----------------
#pragma unroll 3
    for (int l = 0; l < NL; l++) {
        float4 xv = *reinterpret_cast<const float4*>(Cs + l * XP + tn * 4);
        const float* wrow = EW + l * HD + tf * 8;
        ulonglong2 w01 = *reinterpret_cast<const ulonglong2*>(wrow);
        ulonglong2 w23 = *reinterpret_cast<const ulonglong2*>(wrow + 4);
        ull xd[4] = {pack_dup(xv.x), pack_dup(xv.y), pack_dup(xv.z), pack_dup(xv.w)};
#pragma unroll
        for (int i = 0; i < 4; i++) {
            fma2(acc[i][0], xd[i], w01.x);
            fma2(acc[i][1], xd[i], w01.y);
            fma2(acc[i][2], xd[i], w23.x);
            fma2(acc[i][3], xd[i], w23.y);
        }
    }

    // phase-1 epilogue: relu -> As[feat][node]
    {
        float vals[4][8];
#pragma unroll
        for (int i = 0; i < 4; i++) {
#pragma unroll
            for (int j2 = 0; j2 < 4; j2++) {
                float2 p = unpack2(acc[i][j2]);
                vals[i][j2 * 2 + 0] = fmaxf(p.x, 0.f);
                vals[i][j2 * 2 + 1] = fmaxf(p.y, 0.f);
            }
        }
#pragma unroll
        for (int j = 0; j < 8; j++) {
            float4 v = make_float4(vals[0][j], vals[1][j], vals[2][j], vals[3][j]);
            *reinterpret_cast<float4*>(As + (tf * 8 + j) * XP + tn * 4) = v;
        }
    }
    __syncthreads();

    // ---------------- phase 2: a @ W2 ----------------
    {
        ulonglong2 b01 = *reinterpret_cast<const ulonglong2*>(b2 + tf * 8);
        ulonglong2 b23 = *reinterpret_cast<const ulonglong2*>(b2 + tf * 8 + 4);
#pragma unroll
        for (int i = 0; i < 4; i++) {
            acc[i][0] = b01.x; acc[i][1] = b01.y;
            acc[i][2] = b23.x; acc[i][3] = b23.y;
        }
    }

#pragma unroll 8
    for (int kk = 0; kk < HD; kk++) {
        float4 xv = *reinterpret_cast<const float4*>(As + kk * XP + tn * 4);
        const float* wrow = W2 + kk * HD + tf * 8;
        ulonglong2 w01 = *reinterpret_cast<const ulonglong2*>(wrow);
        ulonglong2 w23 = *reinterpret_cast<const ulonglong2*>(wrow + 4);
        ull xd[4] = {pack_dup(xv.x), pack_dup(xv.y), pack_dup(xv.z), pack_dup(xv.w)};
#pragma unroll
        for (int i = 0; i < 4; i++) {
            fma2(acc[i][0], xd[i], w01.x);
            fma2(acc[i][1], xd[i], w01.y);
            fma2(acc[i][2], xd[i], w23.x);
            fma2(acc[i][3], xd[i], w23.y);
        }
    }

#pragma unroll
    for (int i = 0; i < 4; i++) {
        int node = node_base + tn * 4 + i;
        if (node >= n) continue;
        float2 p0 = unpack2(acc[i][0]);
        float2 p1 = unpack2(acc[i][1]);
        float2 p2 = unpack2(acc[i][2]);
        float2 p3 = unpack2(acc[i][3]);
        float* o = out + (size_t)node * HD + tf * 8;
        *reinterpret_cast<float4*>(o) =
            make_float4(fmaxf(p0.x, 0.f), fmaxf(p0.y, 0.f),
                        fmaxf(p1.x, 0.f), fmaxf(p1.y, 0.f));
        *reinterpret_cast<float4*>(o + 4) =
            make_float4(fmaxf(p2.x, 0.f), fmaxf(p2.y, 0.f),
                        fmaxf(p3.x, 0.f), fmaxf(p3.y, 0.f));
    }
}

// ---------------- warp-cooperative edge scatter (layer1, 64-dim) -------------
template <int DIM>
__global__ void __launch_bounds__(256)
scatter_kernel(const int* __restrict__ src,
               const int* __restrict__ dst,
               const float* __restrict__ h,
               float* __restrict__ agg, int E)
{
    const int LPE = DIM / 4;
    const int EPW = 32 / LPE;
    int warp = (blockIdx.x * blockDim.x + threadIdx.x) >> 5;
    int lane = threadIdx.x & 31;
    int base = warp * 32;
    if (base >= E) return;

    int s = 0, d = 0;
    if (base + lane < E) {
        s = __ldg(&src[base + lane]);
        d = __ldg(&dst[base + lane]);
    }

    const int sub = lane / LPE;
    const int j4  = lane % LPE;
    int m = E - base; if (m > 32) m = 32;

    if (m == 32) {
#pragma unroll
        for (int j = 0; j < 32; j += EPW) {
            int eidx = j + sub;
            int es = __shfl_sync(0xFFFFFFFFu, s, eidx);
            int ed = __shfl_sync(0xFFFFFFFFu, d, eidx);
            float4 v = *reinterpret_cast<const float4*>(h + (size_t)es * DIM + j4 * 4);
            atomicAdd(reinterpret_cast<float4*>(agg + (size_t)ed * DIM + j4 * 4), v);
        }
    } else {
        for (int j = 0; j < m; j += EPW) {
            int eidx = j + sub;
            int es = __shfl_sync(0xFFFFFFFFu, s, eidx & 31);
            int ed = __shfl_sync(0xFFFFFFFFu, d, eidx & 31);
            if (eidx < m) {
                float4 v = *reinterpret_cast<const float4*>(h + (size_t)es * DIM + j4 * 4);
                atomicAdd(reinterpret_cast<float4*>(agg + (size_t)ed * DIM + j4 * 4), v);
            }
        }
    }
}

// ---------------- fused 2-layer MLP (layer1) + mean-pool ---------------------
template <int K1>
__global__ void __launch_bounds__(256)
mlp2_kernel(const float* __restrict__ x1, const float* __restrict__ x2,
            const float* __restrict__ W1, const float* __restrict__ b1,
            const float* __restrict__ W2, const float* __restrict__ b2,
            const int* __restrict__ gids,
            float* __restrict__ sums, float* __restrict__ cnts, int n)
{
    __shared__ float As[HD * XP];
    __shared__ float Xs[16 * XP];

    const int tid = threadIdx.x;
    const int node_base = blockIdx.x * 128;
    const int tn = tid & 31;
    const int tf = tid >> 5;

    ull acc[4][4];
    {
        ulonglong2 b01 = *reinterpret_cast<const ulonglong2*>(b1 + tf * 8);
        ulonglong2 b23 = *reinterpret_cast<const ulonglong2*>(b1 + tf * 8 + 4);
#pragma unroll
        for (int i = 0; i < 4; i++) {
            acc[i][0] = b01.x; acc[i][1] = b01.y;
            acc[i][2] = b23.x; acc[i][3] = b23.y;
        }
    }

    for (int kc = 0; kc < K1; kc += 16) {
        if (kc > 0) __syncthreads();
#pragma unroll
        for (int i = tid; i < 128 * 4; i += 256) {
            int nn = i & 127;
            int c  = i >> 7;
            int node = node_base + nn;
            float4 v = make_float4(0.f, 0.f, 0.f, 0.f);
            if (node < n) {
                v = *reinterpret_cast<const float4*>(x1 + (size_t)node * K1 + kc + c * 4);
                float4 u = *reinterpret_cast<const float4*>(x2 + (size_t)node * K1 + kc + c * 4);
                v.x += u.x; v.y += u.y; v.z += u.z; v.w += u.w;
            }
            Xs[(c * 4 + 0) * XP + nn] = v.x;
            Xs[(c * 4 + 1) * XP + nn] = v.y;
            Xs[(c * 4 + 2) * XP + nn] = v.z;
            Xs[(c * 4 + 3) * XP + nn] = v.w;
        }
        __syncthreads();

#pragma unroll
        for (int kk = 0; kk < 16; kk++) {
            float4 xv = *reinterpret_cast<const float4*>(Xs + kk * XP + tn * 4);
            const float* wrow = W1 + (kc + kk) * HD + tf * 8;
            ulonglong2 w01 = *reinterpret_cast<const ulonglong2*>(wrow);
            ulonglong2 w23 = *reinterpret_cast<const ulonglong2*>(wrow + 4);
            ull xd[4] = {pack_dup(xv.x), pack_dup(xv.y), pack_dup(xv.z), pack_dup(xv.w)};
#pragma unroll
            for (int i = 0; i < 4; i++) {
                fma2(acc[i][0], xd[i], w01.x);
                fma2(acc[i][1], xd[i], w01.y);
                fma2(acc[i][2], xd[i], w23.x);
                fma2(acc[i][3], xd[i], w23.y);
            }
        }
    }

    {
        float vals[4][8];
#pragma unroll
        for (int i = 0; i < 4; i++) {
#pragma unroll
            for (int j2 = 0; j2 < 4; j2++) {
                float2 p = unpack2(acc[i][j2]);
                vals[i][j2 * 2 + 0] = fmaxf(p.x, 0.f);
                vals[i][j2 * 2 + 1] = fmaxf(p.y, 0.f);
            }
        }
#pragma unroll
        for (int j = 0; j < 8; j++) {
            float4 v = make_float4(vals[0][j], vals[1][j], vals[2][j], vals[3][j]);
            *reinterpret_cast<float4*>(As + (tf * 8 + j) * XP + tn * 4) = v;
        }
    }
    __syncthreads();

    {
        ulonglong2 b01 = *reinterpret_cast<const ulonglong2*>(b2 + tf * 8);
        ulonglong2 b23 = *reinterpret_cast<const ulonglong2*>(b2 + tf * 8 + 4);
#pragma unroll
        for (int i = 0; i < 4; i++) {
            acc[i][0] = b01.x; acc[i][1] = b01.y;
            acc[i][2] = b23.x; acc[i][3] = b23.y;
        }
    }

#pragma unroll 8
    for (int kk = 0; kk < HD; kk++) {
        float4 xv = *reinterpret_cast<const float4*>(As + kk * XP + tn * 4);
        const float* wrow = W2 + kk * HD + tf * 8;
        ulonglong2 w01 = *reinterpret_cast<const ulonglong2*>(wrow);
        ulonglong2 w23 = *reinterpret_cast<const ulonglong2*>(wrow + 4);
        ull xd[4] = {pack_dup(xv.x), pack_dup(xv.y), pack_dup(xv.z), pack_dup(xv.w)};
#pragma unroll
        for (int i = 0; i < 4; i++) {
            fma2(acc[i][0], xd[i], w01.x);
            fma2(acc[i][1], xd[i], w01.y);
            fma2(acc[i][2], xd[i], w23.x);
            fma2(acc[i][3], xd[i], w23.y);
        }
    }

#pragma unroll
    for (int i = 0; i < 4; i++) {
        int node = node_base + tn * 4 + i;
        if (node >= n) continue;
        float2 p0 = unpack2(acc[i][0]);
        float2 p1 = unpack2(acc[i][1]);
        float2 p2 = unpack2(acc[i][2]);
        float2 p3 = unpack2(acc[i][3]);
        float4 ra = make_float4(fmaxf(p0.x, 0.f), fmaxf(p0.y, 0.f),
                                fmaxf(p1.x, 0.f), fmaxf(p1.y, 0.f));
        float4 rb = make_float4(fmaxf(p2.x, 0.f), fmaxf(p2.y, 0.f),
                                fmaxf(p3.x, 0.f), fmaxf(p3.y, 0.f));
        int g = gids[node];
        float* sg = sums + (size_t)g * HD + tf * 8;
        atomicAdd(reinterpret_cast<float4*>(sg),     ra);
        atomicAdd(reinterpret_cast<float4*>(sg + 4), rb);
        if (tf == 0) atomicAdd(&cnts[g], 1.0f);
    }
}

// ---------------- scorer: out[g] = relu(mean_h @ sw1 + sb1) @ sw2 + sb2 -----
__global__ void scorer_kernel(const float* __restrict__ sums,
                              const float* __restrict__ cnts,
                              const float* __restrict__ sw1,
                              const float* __restrict__ sb1,
                              const float* __restrict__ sw2,
                              const float* __restrict__ sb2,
                              float* __restrict__ out)
{
    int g = blockIdx.x;
    int f = threadIdx.x;           // 64 threads
    float cnt = fmaxf(cnts[g], 1.0f);
    float inv = 1.0f / cnt;
    float acc = sb1[f];
    const float* sg = sums + (size_t)g * HD;
    for (int k = 0; k < HD; k++) acc += (sg[k] * inv) * sw1[k * HD + f];
    float hf = fmaxf(acc, 0.f) * sw2[f];

    __shared__ float red[HD];
    red[f] = hf;
    __syncthreads();
    if (f < 32) red[f] += red[f + 32];
    __syncthreads();
    if (f < 32) {
        float v = red[f];
#pragma unroll
        for (int off = 16; off > 0; off >>= 1)
            v += __shfl_down_sync(0xFFFFFFFFu, v, off);
        if (f == 0) out[g] = v + sb2[0];
    }
}

// ---------------- launcher --------------------------------------------------
extern "C" void kernel_launch(void* const* d_in, const int* in_sizes, int n_in,
                              void* d_out, int out_size)
{
    const int*   labels = (const int*)  d_in[0];
    const int*   src    = (const int*)  d_in[1];
    const int*   dst    = (const int*)  d_in[2];
    const int*   gids   = (const int*)  d_in[3];
    const float* emb    = (const float*)d_in[4];
    const float* w1_0   = (const float*)d_in[5];
    const float* b1_0   = (const float*)d_in[6];
    const float* w2_0   = (const float*)d_in[7];
    const float* b2_0   = (const float*)d_in[8];
    const float* w1_1   = (const float*)d_in[9];
    const float* b1_1   = (const float*)d_in[10];
    const float* w2_1   = (const float*)d_in[11];
    const float* b2_1   = (const float*)d_in[12];
    const float* sw1    = (const float*)d_in[13];
    const float* sb1    = (const float*)d_in[14];
    const float* sw2    = (const float*)d_in[15];
    const float* sb2    = (const float*)d_in[16];
    float* out = (float*)d_out;

    int N = in_sizes[0];
    int E = in_sizes[1];
    int G = out_size;

    if (N > NMAX) N = NMAX;
    if (E > EMAX) E = EMAX;
    if (G > GMAX) G = GMAX;

    u32 *lcnt;
    float *EW, *h1, *ag1, *sums, *cnts;
    cudaGetSymbolAddress((void**)&lcnt, g_lcnt);
    cudaGetSymbolAddress((void**)&EW,   g_EW);
    cudaGetSymbolAddress((void**)&h1,   g_h1);
    cudaGetSymbolAddress((void**)&ag1,  g_ag1);
    cudaGetSymbolAddress((void**)&sums, g_sum);
    cudaGetSymbolAddress((void**)&cnts, g_cnt);

    static bool attr_set = false;
    if (!attr_set) {
        cudaFuncSetAttribute(mlp0_kernel,
                             cudaFuncAttributeMaxDynamicSharedMemorySize,
                             SMEM0_BYTES);
        attr_set = true;
    }

    const int TB = 256;
    const int NB = (N + 127) / 128;                 // MLP node tiles
    const int SB = ((E + 31) / 32 + 7) / 8;         // scatter blocks (8 warps)

    // 1. zero accumulators + seed self-label counts; EW = emb @ W1_0
    init_kernel<<<(N * HD + TB - 1) / TB, TB>>>(labels, N, G, lcnt, ag1, sums, cnts);
    ew_kernel<<<(NL * HD + TB - 1) / TB, TB>>>(emb, w1_0, EW);
    // 2. layer0: label-histogram scatter (1 x 4B atomic per edge)
    label_scatter_kernel<<<(E + TB - 1) / TB, TB>>>(src, dst, labels, lcnt, E);
    // 3. layer0 fused MLP from counts: h1 = relu(relu(cnt'@EW + b1)@W2 + b2)
    mlp0_kernel<<<NB, 256, SMEM0_BYTES>>>(lcnt, EW, b1_0, w2_0, b2_0, h1, N);
    // 4. layer1 scatter: ag1[dst] += h1[src]  (64-dim, warp-cooperative)
    scatter_kernel<HD><<<SB, TB>>>(src, dst, h1, ag1, E);
    // 5. layer1 fused MLP + mean-pool accumulation
    mlp2_kernel<HD><<<NB, 256>>>(h1, ag1, w1_1, b1_1, w2_1, b2_1,
                                 gids, sums, cnts, N);
    // 6. scorer
    scorer_kernel<<<G, HD>>>(sums, cnts, sw1, sb1, sw2, sb2, out);
}

// round 13
// speedup vs baseline: 1.2163x; 1.0250x over previous
#include <cuda_runtime.h>
#include <cuda_bf16.h>

typedef unsigned long long ull;
typedef unsigned int u32;

// ---------------- problem constants (fixed shapes per reference) -------------
#define NMAX   50000
#define EMAX   1250000
#define GMAX   1024
#define LD     32      // label/embedding dim
#define HD     64      // hidden dim
#define NL     51      // number of labels (MAX_LABEL+1)
#define CW     32      // packed u16 count words per node (64 halves >= NL)
#define XP     132     // smem row pitch (floats)

// ---------------- device scratch (no allocation allowed) --------------------
__device__ u32   g_lcnt[NMAX * CW];  // per-node packed u16 label histograms
__device__ float g_EW  [NL * HD];    // emb @ W1_0  (51 x 64)
__device__ float g_h1 [NMAX * HD];   // layer0 output h
__device__ float g_ag1[NMAX * HD];   // layer1 aggregation
__device__ float g_sum[GMAX * HD];   // per-graph feature sums
__device__ float g_cnt[GMAX];        // per-graph node counts

// ---------------- packed f32x2 helpers (Blackwell FFMA2) --------------------
__device__ __forceinline__ void fma2(ull& acc, ull a, ull b) {
    asm("fma.rn.f32x2 %0, %1, %2, %0;" : "+l"(acc) : "l"(a), "l"(b));
}
__device__ __forceinline__ ull pack_dup(float x) {
    ull r;
    asm("mov.b64 %0, {%1, %1};" : "=l"(r) : "r"(__float_as_uint(x)));
    return r;
}
__device__ __forceinline__ float2 unpack2(ull v) {
    unsigned lo, hi;
    asm("mov.b64 {%0, %1}, %2;" : "=r"(lo), "=r"(hi) : "l"(v));
    return make_float2(__uint_as_float(lo), __uint_as_float(hi));
}

// ---------------- init: zero accumulators, seed self-label counts ------------
__global__ void init_kernel(const int* __restrict__ labels, int n, int g,
                            u32* __restrict__ lcnt,
                            float* __restrict__ ag1,
                            float* __restrict__ sums, float* __restrict__ cnts)
{
    int idx = blockIdx.x * blockDim.x + threadIdx.x;
    if (idx < n) {
        uint4 z = make_uint4(0, 0, 0, 0);
        uint4* p = reinterpret_cast<uint4*>(lcnt + (size_t)idx * CW);
#pragma unroll
        for (int w = 0; w < CW / 4; w++) p[w] = z;
        int lab = labels[idx];
        lab = lab < 0 ? 0 : (lab > NL - 1 ? NL - 1 : lab);
        lcnt[(size_t)idx * CW + (lab >> 1)] = 1u << ((lab & 1) * 16);
    }
    if (idx < n * HD) ag1[idx] = 0.f;
    if (idx < g * HD) sums[idx] = 0.f;
    if (idx < g)      cnts[idx] = 0.f;
}

// ---------------- EW = emb @ W1_0  (51 x 64, tiny) ---------------------------
__global__ void ew_kernel(const float* __restrict__ emb,
                          const float* __restrict__ W1,
                          float* __restrict__ EW)
{
    int idx = blockIdx.x * blockDim.x + threadIdx.x;
    if (idx >= NL * HD) return;
    int l = idx / HD, f = idx % HD;
    float s = 0.f;
#pragma unroll
    for (int k = 0; k < LD; k++) s += emb[l * LD + k] * W1[k * HD + f];
    EW[idx] = s;
}

// ---------------- layer0 edge pass: label histogram scatter ------------------
__global__ void __launch_bounds__(256)
label_scatter_kernel(const int* __restrict__ src, const int* __restrict__ dst,
                     const int* __restrict__ labels, u32* __restrict__ lcnt, int E)
{
    int e = blockIdx.x * blockDim.x + threadIdx.x;
    if (e >= E) return;
    int s = __ldg(&src[e]);
    int d = __ldg(&dst[e]);
    int lab = __ldg(&labels[s]);
    lab = lab < 0 ? 0 : (lab > NL - 1 ? NL - 1 : lab);
    atomicAdd(&lcnt[(size_t)d * CW + (lab >> 1)], 1u << ((lab & 1) * 16));
}

// ---------------- layer0 fused MLP from label counts -------------------------
// phase 1: a = relu(b1 + cnt' @ EW)    (K = 51, counts staged as floats)
// phase 2: h1 = relu(a @ W2 + b2)
// Single aliased smem buffer [64][XP]: counts (rows 0..51) during phase 1,
// then overwritten by the intermediate As (rows 0..63) for phase 2.
__global__ void __launch_bounds__(256, 4)
mlp0_kernel(const u32* __restrict__ lcnt,
            const float* __restrict__ EW, const float* __restrict__ b1,
            const float* __restrict__ W2, const float* __restrict__ b2,
            float* __restrict__ out, int n)
{
    __shared__ float buf[HD * XP];    // 33.8 KB, aliased Cs/As

    const int tid = threadIdx.x;
    const int node_base = blockIdx.x * 128;
    const int tn = tid & 31;
    const int tf = tid >> 5;

    // stage counts -> buf[label][node] as floats
#pragma unroll
    for (int i = tid; i < 128 * 7; i += 256) {
        int nn = i & 127;
        int c  = i >> 7;              // word group 0..6 -> labels c*8 .. c*8+7
        int node = node_base + nn;
        uint4 w = make_uint4(0, 0, 0, 0);
        if (node < n)
            w = *reinterpret_cast<const uint4*>(lcnt + (size_t)node * CW + c * 4);
        u32 ws[4] = {w.x, w.y, w.z, w.w};
#pragma unroll
        for (int j = 0; j < 4; j++) {
            int l0 = c * 8 + j * 2;
            if (l0 < NL + 1)     buf[l0 * XP + nn]       = (float)(ws[j] & 0xFFFFu);
            if (l0 + 1 < NL + 1) buf[(l0 + 1) * XP + nn] = (float)(ws[j] >> 16);
        }
    }
    __syncthreads();

    ull acc[4][4];
    {   // init with b1
        ulonglong2 b01 = *reinterpret_cast<const ulonglong2*>(b1 + tf * 8);
        ulonglong2 b23 = *reinterpret_cast<const ulonglong2*>(b1 + tf * 8 + 4);
#pragma unroll
        for (int i = 0; i < 4; i++) {
            acc[i][0] = b01.x; acc[i][1] = b01.y;
            acc[i][2] = b23.x; acc[i][3] = b23.y;
        }
    }

    // phase 1: cnt' @ EW  (51 iterations)
#pragma unroll 3
    for (int l = 0; l < NL; l++) {
        float4 xv = *reinterpret_cast<const float4*>(buf + l * XP + tn * 4);
        const float* wrow = EW + l * HD + tf * 8;
        ulonglong2 w01 = *reinterpret_cast<const ulonglong2*>(wrow);
        ulonglong2 w23 = *reinterpret_cast<const ulonglong2*>(wrow + 4);
        ull xd[4] = {pack_dup(xv.x), pack_dup(xv.y), pack_dup(xv.z), pack_dup(xv.w)};
#pragma unroll
        for (int i = 0; i < 4; i++) {
            fma2(acc[i][0], xd[i], w01.x);
            fma2(acc[i][1], xd[i], w01.y);
            fma2(acc[i][2], xd[i], w23.x);
            fma2(acc[i][3], xd[i], w23.y);
        }
    }
    __syncthreads();                  // all count reads done before As overwrite

    // phase-1 epilogue: relu -> buf[feat][node] (As)
    {
        float vals[4][8];
#pragma unroll
        for (int i = 0; i < 4; i++) {
#pragma unroll
            for (int j2 = 0; j2 < 4; j2++) {
                float2 p = unpack2(acc[i][j2]);
                vals[i][j2 * 2 + 0] = fmaxf(p.x, 0.f);
                vals[i][j2 * 2 + 1] = fmaxf(p.y, 0.f);
            }
        }
#pragma unroll
        for (int j = 0; j < 8; j++) {
            float4 v = make_float4(vals[0][j], vals[1][j], vals[2][j], vals[3][j]);
            *reinterpret_cast<float4*>(buf + (tf * 8 + j) * XP + tn * 4) = v;
        }
    }
    __syncthreads();

    // phase 2: a @ W2
    {
        ulonglong2 b01 = *reinterpret_cast<const ulonglong2*>(b2 + tf * 8);
        ulonglong2 b23 = *reinterpret_cast<const ulonglong2*>(b2 + tf * 8 + 4);
#pragma unroll
        for (int i = 0; i < 4; i++) {
            acc[i][0] = b01.x; acc[i][1] = b01.y;
            acc[i][2] = b23.x; acc[i][3] = b23.y;
        }
    }

#pragma unroll 8
    for (int kk = 0; kk < HD; kk++) {
        float4 xv = *reinterpret_cast<const float4*>(buf + kk * XP + tn * 4);
        const float* wrow = W2 + kk * HD + tf * 8;
        ulonglong2 w01 = *reinterpret_cast<const ulonglong2*>(wrow);
        ulonglong2 w23 = *reinterpret_cast<const ulonglong2*>(wrow + 4);
        ull xd[4] = {pack_dup(xv.x), pack_dup(xv.y), pack_dup(xv.z), pack_dup(xv.w)};
#pragma unroll
        for (int i = 0; i < 4; i++) {
            fma2(acc[i][0], xd[i], w01.x);
            fma2(acc[i][1], xd[i], w01.y);
            fma2(acc[i][2], xd[i], w23.x);
            fma2(acc[i][3], xd[i], w23.y);
        }
    }

#pragma unroll
    for (int i = 0; i < 4; i++) {
        int node = node_base + tn * 4 + i;
        if (node >= n) continue;
        float2 p0 = unpack2(acc[i][0]);
        float2 p1 = unpack2(acc[i][1]);
        float2 p2 = unpack2(acc[i][2]);
        float2 p3 = unpack2(acc[i][3]);
        float* o = out + (size_t)node * HD + tf * 8;
        *reinterpret_cast<float4*>(o) =
            make_float4(fmaxf(p0.x, 0.f), fmaxf(p0.y, 0.f),
                        fmaxf(p1.x, 0.f), fmaxf(p1.y, 0.f));
        *reinterpret_cast<float4*>(o + 4) =
            make_float4(fmaxf(p2.x, 0.f), fmaxf(p2.y, 0.f),
                        fmaxf(p3.x, 0.f), fmaxf(p3.y, 0.f));
    }
}

// ---------------- warp-cooperative edge scatter (layer1, 64-dim) -------------
template <int DIM>
__global__ void __launch_bounds__(256)
scatter_kernel(const int* __restrict__ src,
               const int* __restrict__ dst,
               const float* __restrict__ h,
               float* __restrict__ agg, int E)
{
    const int LPE = DIM / 4;
    const int EPW = 32 / LPE;
    int warp = (blockIdx.x * blockDim.x + threadIdx.x) >> 5;
    int lane = threadIdx.x & 31;
    int base = warp * 32;
    if (base >= E) return;

    int s = 0, d = 0;
    if (base + lane < E) {
        s = __ldg(&src[base + lane]);
        d = __ldg(&dst[base + lane]);
    }

    const int sub = lane / LPE;
    const int j4  = lane % LPE;
    int m = E - base; if (m > 32) m = 32;

    if (m == 32) {
#pragma unroll
        for (int j = 0; j < 32; j += EPW) {
            int eidx = j + sub;
            int es = __shfl_sync(0xFFFFFFFFu, s, eidx);
            int ed = __shfl_sync(0xFFFFFFFFu, d, eidx);
            float4 v = *reinterpret_cast<const float4*>(h + (size_t)es * DIM + j4 * 4);
            atomicAdd(reinterpret_cast<float4*>(agg + (size_t)ed * DIM + j4 * 4), v);
        }
    } else {
        for (int j = 0; j < m; j += EPW) {
            int eidx = j + sub;
            int es = __shfl_sync(0xFFFFFFFFu, s, eidx & 31);
            int ed = __shfl_sync(0xFFFFFFFFu, d, eidx & 31);
            if (eidx < m) {
                float4 v = *reinterpret_cast<const float4*>(h + (size_t)es * DIM + j4 * 4);
                atomicAdd(reinterpret_cast<float4*>(agg + (size_t)ed * DIM + j4 * 4), v);
            }
        }
    }
}

// ---------------- fused 2-layer MLP (layer1) + mean-pool ---------------------
// Single aliased smem buffer [64][XP]: rows 0..15 stage X chunks in phase 1,
// whole buffer holds As for phase 2.
template <int K1>
__global__ void __launch_bounds__(256, 4)
mlp2_kernel(const float* __restrict__ x1, const float* __restrict__ x2,
            const float* __restrict__ W1, const float* __restrict__ b1,
            const float* __restrict__ W2, const float* __restrict__ b2,
            const int* __restrict__ gids,
            float* __restrict__ sums, float* __restrict__ cnts, int n)
{
    __shared__ float buf[HD * XP];    // 33.8 KB, aliased Xs/As

    const int tid = threadIdx.x;
    const int node_base = blockIdx.x * 128;
    const int tn = tid & 31;
    const int tf = tid >> 5;

    ull acc[4][4];
    {
        ulonglong2 b01 = *reinterpret_cast<const ulonglong2*>(b1 + tf * 8);
        ulonglong2 b23 = *reinterpret_cast<const ulonglong2*>(b1 + tf * 8 + 4);
#pragma unroll
        for (int i = 0; i < 4; i++) {
            acc[i][0] = b01.x; acc[i][1] = b01.y;
            acc[i][2] = b23.x; acc[i][3] = b23.y;
        }
    }

    for (int kc = 0; kc < K1; kc += 16) {
        if (kc > 0) __syncthreads();
#pragma unroll
        for (int i = tid; i < 128 * 4; i += 256) {
            int nn = i & 127;
            int c  = i >> 7;
            int node = node_base + nn;
            float4 v = make_float4(0.f, 0.f, 0.f, 0.f);
            if (node < n) {
                v = *reinterpret_cast<const float4*>(x1 + (size_t)node * K1 + kc + c * 4);
                float4 u = *reinterpret_cast<const float4*>(x2 + (size_t)node * K1 + kc + c * 4);
                v.x += u.x; v.y += u.y; v.z += u.z; v.w += u.w;
            }
            buf[(c * 4 + 0) * XP + nn] = v.x;
            buf[(c * 4 + 1) * XP + nn] = v.y;
            buf[(c * 4 + 2) * XP + nn] = v.z;
            buf[(c * 4 + 3) * XP + nn] = v.w;
        }
        __syncthreads();

#pragma unroll
        for (int kk = 0; kk < 16; kk++) {
            float4 xv = *reinterpret_cast<const float4*>(buf + kk * XP + tn * 4);
            const float* wrow = W1 + (kc + kk) * HD + tf * 8;
            ulonglong2 w01 = *reinterpret_cast<const ulonglong2*>(wrow);
            ulonglong2 w23 = *reinterpret_cast<const ulonglong2*>(wrow + 4);
            ull xd[4] = {pack_dup(xv.x), pack_dup(xv.y), pack_dup(xv.z), pack_dup(xv.w)};
#pragma unroll
            for (int i = 0; i < 4; i++) {
                fma2(acc[i][0], xd[i], w01.x);
                fma2(acc[i][1], xd[i], w01.y);
                fma2(acc[i][2], xd[i], w23.x);
                fma2(acc[i][3], xd[i], w23.y);
            }
        }
    }
    __syncthreads();                  // Xs reads done before As overwrite

    {
        float vals[4][8];
#pragma unroll
        for (int i = 0; i < 4; i++) {
#pragma unroll
            for (int j2 = 0; j2 < 4; j2++) {
                float2 p = unpack2(acc[i][j2]);
                vals[i][j2 * 2 + 0] = fmaxf(p.x, 0.f);
                vals[i][j2 * 2 + 1] = fmaxf(p.y, 0.f);
            }
        }
#pragma unroll
        for (int j = 0; j < 8; j++) {
            float4 v = make_float4(vals[0][j], vals[1][j], vals[2][j], vals[3][j]);
            *reinterpret_cast<float4*>(buf + (tf * 8 + j) * XP + tn * 4) = v;
        }
    }
    __syncthreads();

    {
        ulonglong2 b01 = *reinterpret_cast<const ulonglong2*>(b2 + tf * 8);
        ulonglong2 b23 = *reinterpret_cast<const ulonglong2*>(b2 + tf * 8 + 4);
#pragma unroll
        for (int i = 0; i < 4; i++) {
            acc[i][0] = b01.x; acc[i][1] = b01.y;
            acc[i][2] = b23.x; acc[i][3] = b23.y;
        }
    }

#pragma unroll 8
    for (int kk = 0; kk < HD; kk++) {
        float4 xv = *reinterpret_cast<const float4*>(buf + kk * XP + tn * 4);
        const float* wrow = W2 + kk * HD + tf * 8;
        ulonglong2 w01 = *reinterpret_cast<const ulonglong2*>(wrow);
        ulonglong2 w23 = *reinterpret_cast<const ulonglong2*>(wrow + 4);
        ull xd[4] = {pack_dup(xv.x), pack_dup(xv.y), pack_dup(xv.z), pack_dup(xv.w)};
#pragma unroll
        for (int i = 0; i < 4; i++) {
            fma2(acc[i][0], xd[i], w01.x);
            fma2(acc[i][1], xd[i], w01.y);
            fma2(acc[i][2], xd[i], w23.x);
            fma2(acc[i][3], xd[i], w23.y);
        }
    }

#pragma unroll
    for (int i = 0; i < 4; i++) {
        int node = node_base + tn * 4 + i;
        if (node >= n) continue;
        float2 p0 = unpack2(acc[i][0]);
        float2 p1 = unpack2(acc[i][1]);
        float2 p2 = unpack2(acc[i][2]);
        float2 p3 = unpack2(acc[i][3]);
        float4 ra = make_float4(fmaxf(p0.x, 0.f), fmaxf(p0.y, 0.f),
                                fmaxf(p1.x, 0.f), fmaxf(p1.y, 0.f));
        float4 rb = make_float4(fmaxf(p2.x, 0.f), fmaxf(p2.y, 0.f),
                                fmaxf(p3.x, 0.f), fmaxf(p3.y, 0.f));
        int g = gids[node];
        float* sg = sums + (size_t)g * HD + tf * 8;
        atomicAdd(reinterpret_cast<float4*>(sg),     ra);
        atomicAdd(reinterpret_cast<float4*>(sg + 4), rb);
        if (tf == 0) atomicAdd(&cnts[g], 1.0f);
    }
}

// ---------------- scorer: out[g] = relu(mean_h @ sw1 + sb1) @ sw2 + sb2 -----
__global__ void scorer_kernel(const float* __restrict__ sums,
                              const float* __restrict__ cnts,
                              const float* __restrict__ sw1,
                              const float* __restrict__ sb1,
                              const float* __restrict__ sw2,
                              const float* __restrict__ sb2,
                              float* __restrict__ out)
{
    int g = blockIdx.x;
    int f = threadIdx.x;           // 64 threads
    float cnt = fmaxf(cnts[g], 1.0f);
    float inv = 1.0f / cnt;
    float acc = sb1[f];
    const float* sg = sums + (size_t)g * HD;
    for (int k = 0; k < HD; k++) acc += (sg[k] * inv) * sw1[k * HD + f];
    float hf = fmaxf(acc, 0.f) * sw2[f];

    __shared__ float red[HD];
    red[f] = hf;
    __syncthreads();
    if (f < 32) red[f] += red[f + 32];
    __syncthreads();
    if (f < 32) {
        float v = red[f];
#pragma unroll
        for (int off = 16; off > 0; off >>= 1)
            v += __shfl_down_sync(0xFFFFFFFFu, v, off);
        if (f == 0) out[g] = v + sb2[0];
    }
}

// ---------------- launcher --------------------------------------------------
extern "C" void kernel_launch(void* const* d_in, const int* in_sizes, int n_in,
                              void* d_out, int out_size)
{
    const int*   labels = (const int*)  d_in[0];
    const int*   src    = (const int*)  d_in[1];
    const int*   dst    = (const int*)  d_in[2];
    const int*   gids   = (const int*)  d_in[3];
    const float* emb    = (const float*)d_in[4];
    const float* w1_0   = (const float*)d_in[5];
    const float* b1_0   = (const float*)d_in[6];
    const float* w2_0   = (const float*)d_in[7];
    const float* b2_0   = (const float*)d_in[8];
    const float* w1_1   = (const float*)d_in[9];
    const float* b1_1   = (const float*)d_in[10];
    const float* w2_1   = (const float*)d_in[11];
    const float* b2_1   = (const float*)d_in[12];
    const float* sw1    = (const float*)d_in[13];
    const float* sb1    = (const float*)d_in[14];
    const float* sw2    = (const float*)d_in[15];
    const float* sb2    = (const float*)d_in[16];
    float* out = (float*)d_out;

    int N = in_sizes[0];
    int E = in_sizes[1];
    int G = out_size;

    if (N > NMAX) N = NMAX;
    if (E > EMAX) E = EMAX;
    if (G > GMAX) G = GMAX;

    u32 *lcnt;
    float *EW, *h1, *ag1, *sums, *cnts;
    cudaGetSymbolAddress((void**)&lcnt, g_lcnt);
    cudaGetSymbolAddress((void**)&EW,   g_EW);
    cudaGetSymbolAddress((void**)&h1,   g_h1);
    cudaGetSymbolAddress((void**)&ag1,  g_ag1);
    cudaGetSymbolAddress((void**)&sums, g_sum);
    cudaGetSymbolAddress((void**)&cnts, g_cnt);

    const int TB = 256;
    const int NB = (N + 127) / 128;                 // MLP node tiles
    const int SB = ((E + 31) / 32 + 7) / 8;         // scatter blocks (8 warps)

    // 1. zero accumulators + seed self-label counts; EW = emb @ W1_0
    init_kernel<<<(N * HD + TB - 1) / TB, TB>>>(labels, N, G, lcnt, ag1, sums, cnts);
    ew_kernel<<<(NL * HD + TB - 1) / TB, TB>>>(emb, w1_0, EW);
    // 2. layer0: label-histogram scatter (1 x 4B atomic per edge)
    label_scatter_kernel<<<(E + TB - 1) / TB, TB>>>(src, dst, labels, lcnt, E);
    // 3. layer0 fused MLP from counts: h1 = relu(relu(cnt'@EW + b1)@W2 + b2)
    mlp0_kernel<<<NB, 256>>>(lcnt, EW, b1_0, w2_0, b2_0, h1, N);
    // 4. layer1 scatter: ag1[dst] += h1[src]  (64-dim, warp-cooperative)
    scatter_kernel<HD><<<SB, TB>>>(src, dst, h1, ag1, E);
    // 5. layer1 fused MLP + mean-pool accumulation
    mlp2_kernel<HD><<<NB, 256>>>(h1, ag1, w1_1, b1_1, w2_1, b2_1,
                                 gids, sums, cnts, N);
    // 6. scorer
    scorer_kernel<<<G, HD>>>(sums, cnts, sw1, sb1, sw2, sb2, out);
}